// round 7
// baseline (speedup 1.0000x reference)
#include <cuda_runtime.h>
#include <math.h>

#define N_USERS_C 100000
#define N_ITEMS_C 50000
#define N_NODES_C 150000
#define D_C 64
#define NNZ_C 2400000
#define BATCH_C 2048
#define SCB 256
#define NBLK_SCAN ((N_NODES_C + SCB - 1) / SCB)   // 586

// Scratch buffers (allocation-free rule: device globals)
__device__ float g_side[N_NODES_C * D_C];
__device__ float g_ego1[N_NODES_C * D_C];
__device__ float g_ego2[N_NODES_C * D_C];
__device__ int   g_cnt[N_NODES_C];
__device__ int   g_wpos[N_NODES_C];
__device__ int   g_bsum[1024];
__device__ int4  g_epack[NNZ_C];          // (row, col, val-bits, 0) grouped by row

// Packed fp32x2 FMA (sm_103a): lo/hi lanes independent fp32 FMAs
__device__ __forceinline__ unsigned long long fma2(unsigned long long a,
                                                   unsigned long long b,
                                                   unsigned long long c) {
    unsigned long long d;
    asm("fma.rn.f32x2 %0, %1, %2, %3;" : "=l"(d) : "l"(a), "l"(b), "l"(c));
    return d;
}
__device__ __forceinline__ float lo32(unsigned long long v) {
    return __uint_as_float((unsigned)(v & 0xffffffffull));
}
__device__ __forceinline__ float hi32(unsigned long long v) {
    return __uint_as_float((unsigned)(v >> 32));
}

// ---------------------------------------------------------------------------
// CSR-order build: zero counts -> histogram -> hierarchical scan -> reorder
// ---------------------------------------------------------------------------
__global__ void zero_cnt_kernel(int* __restrict__ cnt) {
    int i = blockIdx.x * blockDim.x + threadIdx.x;
    if (i < N_NODES_C) cnt[i] = 0;
}

__global__ void hist_kernel(const int* __restrict__ rows, int* __restrict__ cnt) {
    int e = blockIdx.x * blockDim.x + threadIdx.x;
    if (e < NNZ_C) atomicAdd(&cnt[rows[e]], 1);
}

__global__ void blocksum_kernel(const int* __restrict__ cnt, int* __restrict__ bsum) {
    __shared__ int s[SCB];
    int i = blockIdx.x * SCB + threadIdx.x;
    s[threadIdx.x] = (i < N_NODES_C) ? cnt[i] : 0;
    __syncthreads();
#pragma unroll
    for (int o = SCB / 2; o > 0; o >>= 1) {
        if (threadIdx.x < o) s[threadIdx.x] += s[threadIdx.x + o];
        __syncthreads();
    }
    if (threadIdx.x == 0) bsum[blockIdx.x] = s[0];
}

__global__ __launch_bounds__(1024)
void scan_bsum_kernel(int* __restrict__ bsum) {
    __shared__ int s[1024];
    int tid = threadIdx.x;
    int v = (tid < NBLK_SCAN) ? bsum[tid] : 0;
    s[tid] = v;
    __syncthreads();
    for (int o = 1; o < 1024; o <<= 1) {
        int a = (tid >= o) ? s[tid - o] : 0;
        __syncthreads();
        s[tid] += a;
        __syncthreads();
    }
    if (tid < NBLK_SCAN) bsum[tid] = s[tid] - v;   // exclusive
}

__global__ void scan_final_kernel(const int* __restrict__ cnt,
                                  const int* __restrict__ bsum,
                                  int* __restrict__ wpos) {
    __shared__ int s[SCB];
    int i = blockIdx.x * SCB + threadIdx.x;
    int v = (i < N_NODES_C) ? cnt[i] : 0;
    s[threadIdx.x] = v;
    __syncthreads();
    for (int o = 1; o < SCB; o <<= 1) {
        int a = (threadIdx.x >= o) ? s[threadIdx.x - o] : 0;
        __syncthreads();
        s[threadIdx.x] += a;
        __syncthreads();
    }
    if (i < N_NODES_C) wpos[i] = bsum[blockIdx.x] + s[threadIdx.x] - v;
}

__global__ void reorder_kernel(const int* __restrict__ rows,
                               const int* __restrict__ cols,
                               const float* __restrict__ vals,
                               int* __restrict__ wpos,
                               int4* __restrict__ epack) {
    int e = blockIdx.x * blockDim.x + threadIdx.x;
    if (e >= NNZ_C) return;
    int r = rows[e];
    int p = atomicAdd(&wpos[r], 1);
    epack[p] = make_int4(r, cols[e], __float_as_int(vals[e]), 0);
}

// ---------------------------------------------------------------------------
// zero: clear the scatter accumulator
// ---------------------------------------------------------------------------
__global__ void zero_kernel(float4* __restrict__ p, int n4) {
    int i = blockIdx.x * blockDim.x + threadIdx.x;
    if (i < n4) p[i] = make_float4(0.f, 0.f, 0.f, 0.f);
}

// ---------------------------------------------------------------------------
// Segmented SpMM over row-sorted edges.
// EPS 16 / 256 threads / 150K slots (round-4 shape) but two fully-unrolled
// batches of 8: 8 edge loads + 8 independent gathers in flight before FMAs.
// ---------------------------------------------------------------------------
#define EPS_C 16   // edges per slot
#define EPB_C 256  // edges per block (16 slots * 16)

__device__ __forceinline__ void red_v4(float4* dst, float4 a) {
    asm volatile("red.global.add.v4.f32 [%0], {%1, %2, %3, %4};"
                 :: "l"(dst), "f"(a.x), "f"(a.y), "f"(a.z), "f"(a.w)
                 : "memory");
}

__global__ __launch_bounds__(256)
void seg_spmm_kernel(const int4* __restrict__ epack,
                     const float4* __restrict__ ego,
                     float4* __restrict__ side) {
    int slot = threadIdx.x >> 4;   // 0..15
    int lane = threadIdx.x & 15;   // float4 slice of the 64-dim row
    int e0 = blockIdx.x * EPB_C + slot * EPS_C;

    float4 acc = make_float4(0.f, 0.f, 0.f, 0.f);
    int cur = -1;

#pragma unroll
    for (int half = 0; half < 2; half++) {
        int e = e0 + half * 8;
        int4 ed[8];
        float4 gv[8];
#pragma unroll
        for (int u = 0; u < 8; u++) ed[u] = epack[e + u];              // broadcast LDG.128
#pragma unroll
        for (int u = 0; u < 8; u++) gv[u] = ego[ed[u].y * 16 + lane];  // coalesced gather
#pragma unroll
        for (int u = 0; u < 8; u++) {
            bool newrow = (ed[u].x != cur);
            if (newrow && cur >= 0)
                red_v4(&side[cur * 16 + lane], acc);
            if (newrow) {
                acc = make_float4(0.f, 0.f, 0.f, 0.f);
                cur = ed[u].x;
            }
            float v = __int_as_float(ed[u].z);
            acc.x = fmaf(v, gv[u].x, acc.x);
            acc.y = fmaf(v, gv[u].y, acc.y);
            acc.z = fmaf(v, gv[u].z, acc.z);
            acc.w = fmaf(v, gv[u].w, acc.w);
        }
    }
    if (cur >= 0)
        red_v4(&side[cur * 16 + lane], acc);
}

// ---------------------------------------------------------------------------
// Dense layer via packed FFMA2 (exact fp32 math):
// out = l2norm(leaky_relu(side@Wg + (ego*side)@Wb + bg + bb))
// ---------------------------------------------------------------------------
#define TM_C 64
#define KDIM_C 128
#define INS_C 132   // even -> 8B-aligned LDS.64 of (k, k+1)

__global__ __launch_bounds__(256)
void dense_kernel(const float4* __restrict__ side,
                  const float4* __restrict__ ego,
                  const float4* __restrict__ Wg, const float* __restrict__ bg,
                  const float4* __restrict__ Wb, const float* __restrict__ bb,
                  float4* __restrict__ out, int numTiles) {
    extern __shared__ float smem[];
    float* Wc2  = smem;                       // [64 kpair][64 col][2]
    float* In   = smem + KDIM_C * D_C;        // [64 row][132]
    float* bsum = In + TM_C * INS_C;          // [64]

    int tid = threadIdx.x;

#pragma unroll
    for (int i = 0; i < 8; i++) {
        int f = tid + i * 256;               // float4 index 0..2047
        int k = f >> 4, c4 = f & 15;
        float4 w = (k < 64) ? Wg[k * 16 + c4] : Wb[(k - 64) * 16 + c4];
        int kp = k >> 1, par = k & 1;
        float* dst = &Wc2[kp * 128 + (c4 * 4) * 2 + par];
        dst[0] = w.x; dst[2] = w.y; dst[4] = w.z; dst[6] = w.w;
    }
    if (tid < 64) bsum[tid] = bg[tid] + bb[tid];
    __syncthreads();

    int rg = tid >> 4;
    int cg = tid & 15;
    float4 bsv = *(float4*)&bsum[cg * 4];

    for (int tile = blockIdx.x; tile < numTiles; tile += gridDim.x) {
        int row0 = tile * TM_C;
        __syncthreads();

#pragma unroll
        for (int i = 0; i < 4; i++) {
            int f = tid + i * 256;
            int r = f >> 4, k4 = f & 15;
            float4 s  = make_float4(0.f, 0.f, 0.f, 0.f);
            float4 pr = make_float4(0.f, 0.f, 0.f, 0.f);
            int grow = row0 + r;
            if (grow < N_NODES_C) {
                s = side[grow * 16 + k4];
                float4 e = ego[grow * 16 + k4];
                pr = make_float4(s.x * e.x, s.y * e.y, s.z * e.z, s.w * e.w);
            }
            *(float4*)&In[r * INS_C + k4 * 4]      = s;
            *(float4*)&In[r * INS_C + 64 + k4 * 4] = pr;
        }
        __syncthreads();

        unsigned long long acc[4][4];
#pragma unroll
        for (int i = 0; i < 4; i++)
#pragma unroll
            for (int j = 0; j < 4; j++) acc[i][j] = 0ull;

        const float* Inr0 = &In[(rg * 4 + 0) * INS_C];
        const float* Inr1 = &In[(rg * 4 + 1) * INS_C];
        const float* Inr2 = &In[(rg * 4 + 2) * INS_C];
        const float* Inr3 = &In[(rg * 4 + 3) * INS_C];
        const unsigned long long* Wp = (const unsigned long long*)Wc2 + cg * 4;

#pragma unroll 4
        for (int kp = 0; kp < KDIM_C / 2; kp++) {
            unsigned long long a0 = *(const unsigned long long*)(Inr0 + 2 * kp);
            unsigned long long a1 = *(const unsigned long long*)(Inr1 + 2 * kp);
            unsigned long long a2 = *(const unsigned long long*)(Inr2 + 2 * kp);
            unsigned long long a3 = *(const unsigned long long*)(Inr3 + 2 * kp);
            ulonglong2 b01 = *(const ulonglong2*)(Wp + kp * 64);
            ulonglong2 b23 = *(const ulonglong2*)(Wp + kp * 64 + 2);
            acc[0][0] = fma2(a0, b01.x, acc[0][0]);
            acc[0][1] = fma2(a0, b01.y, acc[0][1]);
            acc[0][2] = fma2(a0, b23.x, acc[0][2]);
            acc[0][3] = fma2(a0, b23.y, acc[0][3]);
            acc[1][0] = fma2(a1, b01.x, acc[1][0]);
            acc[1][1] = fma2(a1, b01.y, acc[1][1]);
            acc[1][2] = fma2(a1, b23.x, acc[1][2]);
            acc[1][3] = fma2(a1, b23.y, acc[1][3]);
            acc[2][0] = fma2(a2, b01.x, acc[2][0]);
            acc[2][1] = fma2(a2, b01.y, acc[2][1]);
            acc[2][2] = fma2(a2, b23.x, acc[2][2]);
            acc[2][3] = fma2(a2, b23.y, acc[2][3]);
            acc[3][0] = fma2(a3, b01.x, acc[3][0]);
            acc[3][1] = fma2(a3, b01.y, acc[3][1]);
            acc[3][2] = fma2(a3, b23.x, acc[3][2]);
            acc[3][3] = fma2(a3, b23.y, acc[3][3]);
        }

#pragma unroll
        for (int i = 0; i < 4; i++) {
            float v0 = lo32(acc[i][0]) + hi32(acc[i][0]) + bsv.x;
            float v1 = lo32(acc[i][1]) + hi32(acc[i][1]) + bsv.y;
            float v2 = lo32(acc[i][2]) + hi32(acc[i][2]) + bsv.z;
            float v3 = lo32(acc[i][3]) + hi32(acc[i][3]) + bsv.w;
            v0 = (v0 > 0.f) ? v0 : 0.2f * v0;
            v1 = (v1 > 0.f) ? v1 : 0.2f * v1;
            v2 = (v2 > 0.f) ? v2 : 0.2f * v2;
            v3 = (v3 > 0.f) ? v3 : 0.2f * v3;
            float ss = v0 * v0 + v1 * v1 + v2 * v2 + v3 * v3;
#pragma unroll
            for (int o = 8; o > 0; o >>= 1)
                ss += __shfl_xor_sync(0xffffffffu, ss, o);
            float nrm = sqrtf(ss);
            float scl = 1.0f / fmaxf(nrm, 1e-12f);
            int grow = row0 + rg * 4 + i;
            if (grow < N_NODES_C)
                out[grow * 16 + cg] = make_float4(v0 * scl, v1 * scl, v2 * scl, v3 * scl);
        }
    }
}

// ---------------------------------------------------------------------------
// gamma[b] = sum over 3 embeddings of dot(emb[u], emb[N_USERS+item])
// ---------------------------------------------------------------------------
__global__ void gamma_kernel(const float* __restrict__ x,
                             const int* __restrict__ users,
                             const int* __restrict__ items,
                             float* __restrict__ out) {
    int b = blockIdx.x * 8 + (threadIdx.x >> 5);
    if (b >= BATCH_C) return;
    int lane = threadIdx.x & 31;
    int u  = users[b];
    int it = N_USERS_C + items[b];
    long long ub = (long long)u * D_C, ib = (long long)it * D_C;
    float acc = 0.f;
    acc += x[ub + lane]      * x[ib + lane];
    acc += x[ub + 32 + lane] * x[ib + 32 + lane];
    acc += g_ego1[ub + lane]      * g_ego1[ib + lane];
    acc += g_ego1[ub + 32 + lane] * g_ego1[ib + 32 + lane];
    acc += g_ego2[ub + lane]      * g_ego2[ib + lane];
    acc += g_ego2[ub + 32 + lane] * g_ego2[ib + 32 + lane];
#pragma unroll
    for (int o = 16; o > 0; o >>= 1)
        acc += __shfl_xor_sync(0xffffffffu, acc, o);
    if (lane == 0) out[b] = acc;
}

// ---------------------------------------------------------------------------
extern "C" void kernel_launch(void* const* d_in, const int* in_sizes, int n_in,
                              void* d_out, int out_size) {
    const int*   rows = (const int*)d_in[0];
    const int*   cols = (const int*)d_in[1];
    const float* vals = (const float*)d_in[2];
    const float* x    = (const float*)d_in[3];

    const float *Wg0, *bg0, *Wb0, *bb0, *Wg1, *bg1, *Wb1, *bb1;
    const int *users, *items;
    if (in_sizes[4] == BATCH_C) {
        users = (const int*)d_in[4];
        items = (const int*)d_in[5];
        Wg0 = (const float*)d_in[6];  bg0 = (const float*)d_in[7];
        Wb0 = (const float*)d_in[8];  bb0 = (const float*)d_in[9];
        Wg1 = (const float*)d_in[10]; bg1 = (const float*)d_in[11];
        Wb1 = (const float*)d_in[12]; bb1 = (const float*)d_in[13];
    } else {
        Wg0 = (const float*)d_in[4];  bg0 = (const float*)d_in[5];
        Wb0 = (const float*)d_in[6];  bb0 = (const float*)d_in[7];
        Wg1 = (const float*)d_in[8];  bg1 = (const float*)d_in[9];
        Wb1 = (const float*)d_in[10]; bb1 = (const float*)d_in[11];
        users = (const int*)d_in[12];
        items = (const int*)d_in[13];
    }

    float *side, *ego1, *ego2;
    int *cnt, *wpos, *bsum;
    int4 *epack;
    cudaGetSymbolAddress((void**)&side,  g_side);
    cudaGetSymbolAddress((void**)&ego1,  g_ego1);
    cudaGetSymbolAddress((void**)&ego2,  g_ego2);
    cudaGetSymbolAddress((void**)&cnt,   g_cnt);
    cudaGetSymbolAddress((void**)&wpos,  g_wpos);
    cudaGetSymbolAddress((void**)&bsum,  g_bsum);
    cudaGetSymbolAddress((void**)&epack, g_epack);

    int smemBytes = (KDIM_C * D_C + TM_C * INS_C + 64) * (int)sizeof(float);
    cudaFuncSetAttribute(dense_kernel, cudaFuncAttributeMaxDynamicSharedMemorySize, smemBytes);

    int numTiles   = (N_NODES_C + TM_C - 1) / TM_C;       // 2344
    int edgeBlocks = (NNZ_C + 255) / 256;                 // 9375
    int z4 = N_NODES_C * 16;
    int zeroBlocks = (z4 + 255) / 256;
    int spmmBlocks = NNZ_C / EPB_C;                       // 9375

    // Build row-sorted edge list (shared by both layers)
    zero_cnt_kernel<<<NBLK_SCAN, SCB>>>(cnt);
    hist_kernel<<<edgeBlocks, 256>>>(rows, cnt);
    blocksum_kernel<<<NBLK_SCAN, SCB>>>(cnt, bsum);
    scan_bsum_kernel<<<1, 1024>>>(bsum);
    scan_final_kernel<<<NBLK_SCAN, SCB>>>(cnt, bsum, wpos);
    reorder_kernel<<<edgeBlocks, 256>>>(rows, cols, vals, wpos, epack);

    // Layer 1
    zero_kernel<<<zeroBlocks, 256>>>((float4*)side, z4);
    seg_spmm_kernel<<<spmmBlocks, 256>>>(epack, (const float4*)x, (float4*)side);
    dense_kernel<<<592, 256, smemBytes>>>((const float4*)side, (const float4*)x,
                                          (const float4*)Wg0, bg0,
                                          (const float4*)Wb0, bb0,
                                          (float4*)ego1, numTiles);
    // Layer 2
    zero_kernel<<<zeroBlocks, 256>>>((float4*)side, z4);
    seg_spmm_kernel<<<spmmBlocks, 256>>>(epack, (const float4*)ego1, (float4*)side);
    dense_kernel<<<592, 256, smemBytes>>>((const float4*)side, (const float4*)ego1,
                                          (const float4*)Wg1, bg1,
                                          (const float4*)Wb1, bb1,
                                          (float4*)ego2, numTiles);
    // Final BPR scores
    gamma_kernel<<<BATCH_C / 8, 256>>>(x, users, items, (float*)d_out);
}

// round 8
// speedup vs baseline: 1.1207x; 1.1207x over previous
#include <cuda_runtime.h>
#include <math.h>
#include <stdint.h>

#define N_USERS_C 100000
#define N_ITEMS_C 50000
#define N_NODES_C 150000
#define D_C 64
#define NNZ_C 2400000
#define BATCH_C 2048
#define SCB 256
#define NBLK_SCAN ((N_NODES_C + SCB - 1) / SCB)   // 586

// Scratch buffers (allocation-free rule: device globals)
__device__ float g_side[N_NODES_C * D_C];
__device__ float g_ego1[N_NODES_C * D_C];
__device__ float g_ego2[N_NODES_C * D_C];
__device__ int   g_cnt[N_NODES_C];
__device__ int   g_wpos[N_NODES_C];
__device__ int   g_bsum[1024];
__device__ int4  g_epack[NNZ_C];          // (row, col, val-bits, 0) grouped by row

// Packed fp32x2 FMA (sm_103a): lo/hi lanes independent fp32 FMAs
__device__ __forceinline__ unsigned long long fma2(unsigned long long a,
                                                   unsigned long long b,
                                                   unsigned long long c) {
    unsigned long long d;
    asm("fma.rn.f32x2 %0, %1, %2, %3;" : "=l"(d) : "l"(a), "l"(b), "l"(c));
    return d;
}
__device__ __forceinline__ float lo32(unsigned long long v) {
    return __uint_as_float((unsigned)(v & 0xffffffffull));
}
__device__ __forceinline__ float hi32(unsigned long long v) {
    return __uint_as_float((unsigned)(v >> 32));
}

// ---------------------------------------------------------------------------
// CSR-order build: zero counts -> histogram -> hierarchical scan -> reorder
// ---------------------------------------------------------------------------
__global__ void zero_cnt_kernel(int* __restrict__ cnt) {
    int i = blockIdx.x * blockDim.x + threadIdx.x;
    if (i < N_NODES_C) cnt[i] = 0;
}

__global__ void hist_kernel(const int* __restrict__ rows, int* __restrict__ cnt) {
    int e = blockIdx.x * blockDim.x + threadIdx.x;
    if (e < NNZ_C) atomicAdd(&cnt[rows[e]], 1);
}

__global__ void blocksum_kernel(const int* __restrict__ cnt, int* __restrict__ bsum) {
    __shared__ int s[SCB];
    int i = blockIdx.x * SCB + threadIdx.x;
    s[threadIdx.x] = (i < N_NODES_C) ? cnt[i] : 0;
    __syncthreads();
#pragma unroll
    for (int o = SCB / 2; o > 0; o >>= 1) {
        if (threadIdx.x < o) s[threadIdx.x] += s[threadIdx.x + o];
        __syncthreads();
    }
    if (threadIdx.x == 0) bsum[blockIdx.x] = s[0];
}

__global__ __launch_bounds__(1024)
void scan_bsum_kernel(int* __restrict__ bsum) {
    __shared__ int s[1024];
    int tid = threadIdx.x;
    int v = (tid < NBLK_SCAN) ? bsum[tid] : 0;
    s[tid] = v;
    __syncthreads();
    for (int o = 1; o < 1024; o <<= 1) {
        int a = (tid >= o) ? s[tid - o] : 0;
        __syncthreads();
        s[tid] += a;
        __syncthreads();
    }
    if (tid < NBLK_SCAN) bsum[tid] = s[tid] - v;   // exclusive
}

__global__ void scan_final_kernel(const int* __restrict__ cnt,
                                  const int* __restrict__ bsum,
                                  int* __restrict__ wpos) {
    __shared__ int s[SCB];
    int i = blockIdx.x * SCB + threadIdx.x;
    int v = (i < N_NODES_C) ? cnt[i] : 0;
    s[threadIdx.x] = v;
    __syncthreads();
    for (int o = 1; o < SCB; o <<= 1) {
        int a = (threadIdx.x >= o) ? s[threadIdx.x - o] : 0;
        __syncthreads();
        s[threadIdx.x] += a;
        __syncthreads();
    }
    if (i < N_NODES_C) wpos[i] = bsum[blockIdx.x] + s[threadIdx.x] - v;
}

__global__ void reorder_kernel(const int* __restrict__ rows,
                               const int* __restrict__ cols,
                               const float* __restrict__ vals,
                               int* __restrict__ wpos,
                               int4* __restrict__ epack) {
    int e = blockIdx.x * blockDim.x + threadIdx.x;
    if (e >= NNZ_C) return;
    int r = rows[e];
    int p = atomicAdd(&wpos[r], 1);
    epack[p] = make_int4(r, cols[e], __float_as_int(vals[e]), 0);
}

// ---------------------------------------------------------------------------
// zero: clear the scatter accumulator
// ---------------------------------------------------------------------------
__global__ void zero_kernel(float4* __restrict__ p, int n4) {
    int i = blockIdx.x * blockDim.x + threadIdx.x;
    if (i < n4) p[i] = make_float4(0.f, 0.f, 0.f, 0.f);
}

// ---------------------------------------------------------------------------
// Segmented SpMM over row-sorted edges, cp.async edition.
// 16 slots x 16 edges per block. Each lane owns one edge (coalesced LDG.128),
// issues 16 fire-and-forget cp.async 16B gathers into smem (zero register
// pressure, 16 in flight), then computes from smem with row-change RED flush.
// NNZ = 9375 * 256 exactly -> no tails.
// ---------------------------------------------------------------------------
#define EPS_C 16   // edges per slot
#define EPB_C 256  // edges per block (16 slots * 16)

__device__ __forceinline__ void red_v4(float4* dst, float4 a) {
    asm volatile("red.global.add.v4.f32 [%0], {%1, %2, %3, %4};"
                 :: "l"(dst), "f"(a.x), "f"(a.y), "f"(a.z), "f"(a.w)
                 : "memory");
}

__global__ __launch_bounds__(256)
void seg_spmm_kernel(const int4* __restrict__ epack,
                     const float4* __restrict__ ego,
                     float4* __restrict__ side) {
    extern __shared__ float4 sbuf[];     // [256 edges][16 lanes] = 64KB
    int tid  = threadIdx.x;
    int slot = tid >> 4;                 // 0..15
    int lane = tid & 15;                 // float4 slice of the 64-dim row
    int half = (tid & 31) >= 16 ? 16 : 0;  // shfl base within the 32-lane warp
    int e0 = blockIdx.x * EPB_C + slot * EPS_C;

    // Each lane loads its own edge: 16 consecutive int4 per slot -> coalesced
    int4 ep = epack[e0 + lane];

    // Issue 16 gathers (one per edge in this slot); lanes contiguous -> 256B/edge
    uint32_t sbase = (uint32_t)__cvta_generic_to_shared(sbuf);
#pragma unroll
    for (int u = 0; u < 16; u++) {
        int c = __shfl_sync(0xffffffffu, ep.y, half + u);
        const float4* src = &ego[c * 16 + lane];
        uint32_t dst = sbase + (uint32_t)(((slot * 16 + u) * 16 + lane) * 16);
        asm volatile("cp.async.cg.shared.global [%0], [%1], 16;"
                     :: "r"(dst), "l"(src) : "memory");
    }
    asm volatile("cp.async.commit_group;" ::: "memory");
    asm volatile("cp.async.wait_group 0;" ::: "memory");

    // Compute: walk the 16 sorted edges, flush on row change
    float4 acc = make_float4(0.f, 0.f, 0.f, 0.f);
    int cur = -1;
#pragma unroll
    for (int u = 0; u < 16; u++) {
        int   r = __shfl_sync(0xffffffffu, ep.x, half + u);
        float v = __int_as_float(__shfl_sync(0xffffffffu, ep.z, half + u));
        float4 gv = sbuf[(slot * 16 + u) * 16 + lane];
        if (r != cur) {
            if (cur >= 0) red_v4(&side[cur * 16 + lane], acc);
            acc = make_float4(0.f, 0.f, 0.f, 0.f);
            cur = r;
        }
        acc.x = fmaf(v, gv.x, acc.x);
        acc.y = fmaf(v, gv.y, acc.y);
        acc.z = fmaf(v, gv.z, acc.z);
        acc.w = fmaf(v, gv.w, acc.w);
    }
    if (cur >= 0)
        red_v4(&side[cur * 16 + lane], acc);
}

// ---------------------------------------------------------------------------
// Dense layer via packed FFMA2 (exact fp32 math):
// out = l2norm(leaky_relu(side@Wg + (ego*side)@Wb + bg + bb))
// ---------------------------------------------------------------------------
#define TM_C 64
#define KDIM_C 128
#define INS_C 132   // even -> 8B-aligned LDS.64 of (k, k+1)

__global__ __launch_bounds__(256)
void dense_kernel(const float4* __restrict__ side,
                  const float4* __restrict__ ego,
                  const float4* __restrict__ Wg, const float* __restrict__ bg,
                  const float4* __restrict__ Wb, const float* __restrict__ bb,
                  float4* __restrict__ out, int numTiles) {
    extern __shared__ float smem[];
    float* Wc2  = smem;                       // [64 kpair][64 col][2]
    float* In   = smem + KDIM_C * D_C;        // [64 row][132]
    float* bsum = In + TM_C * INS_C;          // [64]

    int tid = threadIdx.x;

#pragma unroll
    for (int i = 0; i < 8; i++) {
        int f = tid + i * 256;               // float4 index 0..2047
        int k = f >> 4, c4 = f & 15;
        float4 w = (k < 64) ? Wg[k * 16 + c4] : Wb[(k - 64) * 16 + c4];
        int kp = k >> 1, par = k & 1;
        float* dst = &Wc2[kp * 128 + (c4 * 4) * 2 + par];
        dst[0] = w.x; dst[2] = w.y; dst[4] = w.z; dst[6] = w.w;
    }
    if (tid < 64) bsum[tid] = bg[tid] + bb[tid];
    __syncthreads();

    int rg = tid >> 4;
    int cg = tid & 15;
    float4 bsv = *(float4*)&bsum[cg * 4];

    for (int tile = blockIdx.x; tile < numTiles; tile += gridDim.x) {
        int row0 = tile * TM_C;
        __syncthreads();

#pragma unroll
        for (int i = 0; i < 4; i++) {
            int f = tid + i * 256;
            int r = f >> 4, k4 = f & 15;
            float4 s  = make_float4(0.f, 0.f, 0.f, 0.f);
            float4 pr = make_float4(0.f, 0.f, 0.f, 0.f);
            int grow = row0 + r;
            if (grow < N_NODES_C) {
                s = side[grow * 16 + k4];
                float4 e = ego[grow * 16 + k4];
                pr = make_float4(s.x * e.x, s.y * e.y, s.z * e.z, s.w * e.w);
            }
            *(float4*)&In[r * INS_C + k4 * 4]      = s;
            *(float4*)&In[r * INS_C + 64 + k4 * 4] = pr;
        }
        __syncthreads();

        unsigned long long acc[4][4];
#pragma unroll
        for (int i = 0; i < 4; i++)
#pragma unroll
            for (int j = 0; j < 4; j++) acc[i][j] = 0ull;

        const float* Inr0 = &In[(rg * 4 + 0) * INS_C];
        const float* Inr1 = &In[(rg * 4 + 1) * INS_C];
        const float* Inr2 = &In[(rg * 4 + 2) * INS_C];
        const float* Inr3 = &In[(rg * 4 + 3) * INS_C];
        const unsigned long long* Wp = (const unsigned long long*)Wc2 + cg * 4;

#pragma unroll 4
        for (int kp = 0; kp < KDIM_C / 2; kp++) {
            unsigned long long a0 = *(const unsigned long long*)(Inr0 + 2 * kp);
            unsigned long long a1 = *(const unsigned long long*)(Inr1 + 2 * kp);
            unsigned long long a2 = *(const unsigned long long*)(Inr2 + 2 * kp);
            unsigned long long a3 = *(const unsigned long long*)(Inr3 + 2 * kp);
            ulonglong2 b01 = *(const ulonglong2*)(Wp + kp * 64);
            ulonglong2 b23 = *(const ulonglong2*)(Wp + kp * 64 + 2);
            acc[0][0] = fma2(a0, b01.x, acc[0][0]);
            acc[0][1] = fma2(a0, b01.y, acc[0][1]);
            acc[0][2] = fma2(a0, b23.x, acc[0][2]);
            acc[0][3] = fma2(a0, b23.y, acc[0][3]);
            acc[1][0] = fma2(a1, b01.x, acc[1][0]);
            acc[1][1] = fma2(a1, b01.y, acc[1][1]);
            acc[1][2] = fma2(a1, b23.x, acc[1][2]);
            acc[1][3] = fma2(a1, b23.y, acc[1][3]);
            acc[2][0] = fma2(a2, b01.x, acc[2][0]);
            acc[2][1] = fma2(a2, b01.y, acc[2][1]);
            acc[2][2] = fma2(a2, b23.x, acc[2][2]);
            acc[2][3] = fma2(a2, b23.y, acc[2][3]);
            acc[3][0] = fma2(a3, b01.x, acc[3][0]);
            acc[3][1] = fma2(a3, b01.y, acc[3][1]);
            acc[3][2] = fma2(a3, b23.x, acc[3][2]);
            acc[3][3] = fma2(a3, b23.y, acc[3][3]);
        }

#pragma unroll
        for (int i = 0; i < 4; i++) {
            float v0 = lo32(acc[i][0]) + hi32(acc[i][0]) + bsv.x;
            float v1 = lo32(acc[i][1]) + hi32(acc[i][1]) + bsv.y;
            float v2 = lo32(acc[i][2]) + hi32(acc[i][2]) + bsv.z;
            float v3 = lo32(acc[i][3]) + hi32(acc[i][3]) + bsv.w;
            v0 = (v0 > 0.f) ? v0 : 0.2f * v0;
            v1 = (v1 > 0.f) ? v1 : 0.2f * v1;
            v2 = (v2 > 0.f) ? v2 : 0.2f * v2;
            v3 = (v3 > 0.f) ? v3 : 0.2f * v3;
            float ss = v0 * v0 + v1 * v1 + v2 * v2 + v3 * v3;
#pragma unroll
            for (int o = 8; o > 0; o >>= 1)
                ss += __shfl_xor_sync(0xffffffffu, ss, o);
            float nrm = sqrtf(ss);
            float scl = 1.0f / fmaxf(nrm, 1e-12f);
            int grow = row0 + rg * 4 + i;
            if (grow < N_NODES_C)
                out[grow * 16 + cg] = make_float4(v0 * scl, v1 * scl, v2 * scl, v3 * scl);
        }
    }
}

// ---------------------------------------------------------------------------
// gamma[b] = sum over 3 embeddings of dot(emb[u], emb[N_USERS+item])
// ---------------------------------------------------------------------------
__global__ void gamma_kernel(const float* __restrict__ x,
                             const int* __restrict__ users,
                             const int* __restrict__ items,
                             float* __restrict__ out) {
    int b = blockIdx.x * 8 + (threadIdx.x >> 5);
    if (b >= BATCH_C) return;
    int lane = threadIdx.x & 31;
    int u  = users[b];
    int it = N_USERS_C + items[b];
    long long ub = (long long)u * D_C, ib = (long long)it * D_C;
    float acc = 0.f;
    acc += x[ub + lane]      * x[ib + lane];
    acc += x[ub + 32 + lane] * x[ib + 32 + lane];
    acc += g_ego1[ub + lane]      * g_ego1[ib + lane];
    acc += g_ego1[ub + 32 + lane] * g_ego1[ib + 32 + lane];
    acc += g_ego2[ub + lane]      * g_ego2[ib + lane];
    acc += g_ego2[ub + 32 + lane] * g_ego2[ib + 32 + lane];
#pragma unroll
    for (int o = 16; o > 0; o >>= 1)
        acc += __shfl_xor_sync(0xffffffffu, acc, o);
    if (lane == 0) out[b] = acc;
}

// ---------------------------------------------------------------------------
extern "C" void kernel_launch(void* const* d_in, const int* in_sizes, int n_in,
                              void* d_out, int out_size) {
    const int*   rows = (const int*)d_in[0];
    const int*   cols = (const int*)d_in[1];
    const float* vals = (const float*)d_in[2];
    const float* x    = (const float*)d_in[3];

    const float *Wg0, *bg0, *Wb0, *bb0, *Wg1, *bg1, *Wb1, *bb1;
    const int *users, *items;
    if (in_sizes[4] == BATCH_C) {
        users = (const int*)d_in[4];
        items = (const int*)d_in[5];
        Wg0 = (const float*)d_in[6];  bg0 = (const float*)d_in[7];
        Wb0 = (const float*)d_in[8];  bb0 = (const float*)d_in[9];
        Wg1 = (const float*)d_in[10]; bg1 = (const float*)d_in[11];
        Wb1 = (const float*)d_in[12]; bb1 = (const float*)d_in[13];
    } else {
        Wg0 = (const float*)d_in[4];  bg0 = (const float*)d_in[5];
        Wb0 = (const float*)d_in[6];  bb0 = (const float*)d_in[7];
        Wg1 = (const float*)d_in[8];  bg1 = (const float*)d_in[9];
        Wb1 = (const float*)d_in[10]; bb1 = (const float*)d_in[11];
        users = (const int*)d_in[12];
        items = (const int*)d_in[13];
    }

    float *side, *ego1, *ego2;
    int *cnt, *wpos, *bsum;
    int4 *epack;
    cudaGetSymbolAddress((void**)&side,  g_side);
    cudaGetSymbolAddress((void**)&ego1,  g_ego1);
    cudaGetSymbolAddress((void**)&ego2,  g_ego2);
    cudaGetSymbolAddress((void**)&cnt,   g_cnt);
    cudaGetSymbolAddress((void**)&wpos,  g_wpos);
    cudaGetSymbolAddress((void**)&bsum,  g_bsum);
    cudaGetSymbolAddress((void**)&epack, g_epack);

    int smemBytes = (KDIM_C * D_C + TM_C * INS_C + 64) * (int)sizeof(float);
    cudaFuncSetAttribute(dense_kernel, cudaFuncAttributeMaxDynamicSharedMemorySize, smemBytes);
    int spmmSmem = EPB_C * 16 * 16;   // 65536
    cudaFuncSetAttribute(seg_spmm_kernel, cudaFuncAttributeMaxDynamicSharedMemorySize, spmmSmem);

    int numTiles   = (N_NODES_C + TM_C - 1) / TM_C;       // 2344
    int edgeBlocks = (NNZ_C + 255) / 256;                 // 9375
    int z4 = N_NODES_C * 16;
    int zeroBlocks = (z4 + 255) / 256;
    int spmmBlocks = NNZ_C / EPB_C;                       // 9375

    // Build row-sorted edge list (shared by both layers)
    zero_cnt_kernel<<<NBLK_SCAN, SCB>>>(cnt);
    hist_kernel<<<edgeBlocks, 256>>>(rows, cnt);
    blocksum_kernel<<<NBLK_SCAN, SCB>>>(cnt, bsum);
    scan_bsum_kernel<<<1, 1024>>>(bsum);
    scan_final_kernel<<<NBLK_SCAN, SCB>>>(cnt, bsum, wpos);
    reorder_kernel<<<edgeBlocks, 256>>>(rows, cols, vals, wpos, epack);

    // Layer 1
    zero_kernel<<<zeroBlocks, 256>>>((float4*)side, z4);
    seg_spmm_kernel<<<spmmBlocks, 256, spmmSmem>>>(epack, (const float4*)x, (float4*)side);
    dense_kernel<<<592, 256, smemBytes>>>((const float4*)side, (const float4*)x,
                                          (const float4*)Wg0, bg0,
                                          (const float4*)Wb0, bb0,
                                          (float4*)ego1, numTiles);
    // Layer 2
    zero_kernel<<<zeroBlocks, 256>>>((float4*)side, z4);
    seg_spmm_kernel<<<spmmBlocks, 256, spmmSmem>>>(epack, (const float4*)ego1, (float4*)side);
    dense_kernel<<<592, 256, smemBytes>>>((const float4*)side, (const float4*)ego1,
                                          (const float4*)Wg1, bg1,
                                          (const float4*)Wb1, bb1,
                                          (float4*)ego2, numTiles);
    // Final BPR scores
    gamma_kernel<<<BATCH_C / 8, 256>>>(x, users, items, (float*)d_out);
}

// round 9
// speedup vs baseline: 1.1587x; 1.0339x over previous
#include <cuda_runtime.h>
#include <math.h>
#include <stdint.h>

#define N_USERS_C 100000
#define N_ITEMS_C 50000
#define N_NODES_C 150000
#define D_C 64
#define NNZ_C 2400000
#define BATCH_C 2048
#define SCB 256
#define NBLK_SCAN ((N_NODES_C + SCB - 1) / SCB)   // 586

// Scratch buffers (allocation-free rule: device globals)
__device__ float g_side[N_NODES_C * D_C];
__device__ float g_ego1[N_NODES_C * D_C];
__device__ float g_ego2[N_NODES_C * D_C];
__device__ int   g_cnt[N_NODES_C];
__device__ int   g_wpos[N_NODES_C];
__device__ int   g_bsum[1024];
__device__ int4  g_epack[NNZ_C];          // (row, col, val-bits, 0) grouped by row

// Packed fp32x2 FMA (sm_103a): lo/hi lanes independent fp32 FMAs
__device__ __forceinline__ unsigned long long fma2(unsigned long long a,
                                                   unsigned long long b,
                                                   unsigned long long c) {
    unsigned long long d;
    asm("fma.rn.f32x2 %0, %1, %2, %3;" : "=l"(d) : "l"(a), "l"(b), "l"(c));
    return d;
}
__device__ __forceinline__ float lo32(unsigned long long v) {
    return __uint_as_float((unsigned)(v & 0xffffffffull));
}
__device__ __forceinline__ float hi32(unsigned long long v) {
    return __uint_as_float((unsigned)(v >> 32));
}

// ---------------------------------------------------------------------------
// CSR-order build: zero counts -> histogram -> hierarchical scan -> reorder
// ---------------------------------------------------------------------------
__global__ void zero_cnt_kernel(int* __restrict__ cnt) {
    int i = blockIdx.x * blockDim.x + threadIdx.x;
    if (i < N_NODES_C) cnt[i] = 0;
}

__global__ void hist_kernel(const int* __restrict__ rows, int* __restrict__ cnt) {
    int e = blockIdx.x * blockDim.x + threadIdx.x;
    if (e < NNZ_C) atomicAdd(&cnt[rows[e]], 1);
}

__global__ void blocksum_kernel(const int* __restrict__ cnt, int* __restrict__ bsum) {
    __shared__ int s[SCB];
    int i = blockIdx.x * SCB + threadIdx.x;
    s[threadIdx.x] = (i < N_NODES_C) ? cnt[i] : 0;
    __syncthreads();
#pragma unroll
    for (int o = SCB / 2; o > 0; o >>= 1) {
        if (threadIdx.x < o) s[threadIdx.x] += s[threadIdx.x + o];
        __syncthreads();
    }
    if (threadIdx.x == 0) bsum[blockIdx.x] = s[0];
}

__global__ __launch_bounds__(1024)
void scan_bsum_kernel(int* __restrict__ bsum) {
    __shared__ int s[1024];
    int tid = threadIdx.x;
    int v = (tid < NBLK_SCAN) ? bsum[tid] : 0;
    s[tid] = v;
    __syncthreads();
    for (int o = 1; o < 1024; o <<= 1) {
        int a = (tid >= o) ? s[tid - o] : 0;
        __syncthreads();
        s[tid] += a;
        __syncthreads();
    }
    if (tid < NBLK_SCAN) bsum[tid] = s[tid] - v;   // exclusive
}

__global__ void scan_final_kernel(const int* __restrict__ cnt,
                                  const int* __restrict__ bsum,
                                  int* __restrict__ wpos) {
    __shared__ int s[SCB];
    int i = blockIdx.x * SCB + threadIdx.x;
    int v = (i < N_NODES_C) ? cnt[i] : 0;
    s[threadIdx.x] = v;
    __syncthreads();
    for (int o = 1; o < SCB; o <<= 1) {
        int a = (threadIdx.x >= o) ? s[threadIdx.x - o] : 0;
        __syncthreads();
        s[threadIdx.x] += a;
        __syncthreads();
    }
    if (i < N_NODES_C) wpos[i] = bsum[blockIdx.x] + s[threadIdx.x] - v;
}

__global__ void reorder_kernel(const int* __restrict__ rows,
                               const int* __restrict__ cols,
                               const float* __restrict__ vals,
                               int* __restrict__ wpos,
                               int4* __restrict__ epack) {
    int e = blockIdx.x * blockDim.x + threadIdx.x;
    if (e >= NNZ_C) return;
    int r = rows[e];
    int p = atomicAdd(&wpos[r], 1);
    epack[p] = make_int4(r, cols[e], __float_as_int(vals[e]), 0);
}

// ---------------------------------------------------------------------------
// zero: clear the scatter accumulator
// ---------------------------------------------------------------------------
__global__ void zero_kernel(float4* __restrict__ p, int n4) {
    int i = blockIdx.x * blockDim.x + threadIdx.x;
    if (i < n4) p[i] = make_float4(0.f, 0.f, 0.f, 0.f);
}

// ---------------------------------------------------------------------------
// Segmented SpMM over row-sorted edges, D-HALF pass edition.
// Each launch covers 32 of the 64 dims (halfOff = 0 or 8 float4s), so the
// pass's random working set (ego half 19.2MB + side half 19.2MB) fits L2.
// 32 slots x 8 lanes per block; slot walks 8 sorted edges (each lane owns
// one edge load); batch-4 gathers; RED flush on row change.
// NNZ = 9375 * 256 exactly -> no tails.
// ---------------------------------------------------------------------------
#define HEPS_C 8    // edges per slot
#define HEPB_C 256  // edges per block (32 slots * 8)

__device__ __forceinline__ void red_v4(float4* dst, float4 a) {
    asm volatile("red.global.add.v4.f32 [%0], {%1, %2, %3, %4};"
                 :: "l"(dst), "f"(a.x), "f"(a.y), "f"(a.z), "f"(a.w)
                 : "memory");
}

__global__ __launch_bounds__(256)
void seg_spmm_half_kernel(const int4* __restrict__ epack,
                          const float4* __restrict__ ego,
                          float4* __restrict__ side,
                          int halfOff) {
    int slot = threadIdx.x >> 3;          // 0..31
    int lane = threadIdx.x & 7;           // float4 slice within the 32-dim half
    int lbase = threadIdx.x & 24;         // shfl base of this slot inside warp
    int e0 = blockIdx.x * HEPB_C + slot * HEPS_C;

    // Each lane owns exactly one edge of its slot: coalesced 128B per slot
    int4 ep = epack[e0 + lane];

    float4 acc = make_float4(0.f, 0.f, 0.f, 0.f);
    int cur = -1;

#pragma unroll
    for (int b = 0; b < 2; b++) {
        int rr[4]; float vv[4]; float4 gv[4];
#pragma unroll
        for (int u = 0; u < 4; u++) {
            int src = lbase + b * 4 + u;
            int c = __shfl_sync(0xffffffffu, ep.y, src);
            rr[u] = __shfl_sync(0xffffffffu, ep.x, src);
            vv[u] = __int_as_float(__shfl_sync(0xffffffffu, ep.z, src));
            gv[u] = ego[c * 16 + halfOff + lane];   // coalesced 128B per edge
        }
#pragma unroll
        for (int u = 0; u < 4; u++) {
            if (rr[u] != cur) {
                if (cur >= 0) red_v4(&side[cur * 16 + halfOff + lane], acc);
                acc = make_float4(0.f, 0.f, 0.f, 0.f);
                cur = rr[u];
            }
            acc.x = fmaf(vv[u], gv[u].x, acc.x);
            acc.y = fmaf(vv[u], gv[u].y, acc.y);
            acc.z = fmaf(vv[u], gv[u].z, acc.z);
            acc.w = fmaf(vv[u], gv[u].w, acc.w);
        }
    }
    if (cur >= 0)
        red_v4(&side[cur * 16 + halfOff + lane], acc);
}

// ---------------------------------------------------------------------------
// Dense layer via packed FFMA2 (exact fp32 math):
// out = l2norm(leaky_relu(side@Wg + (ego*side)@Wb + bg + bb))
// ---------------------------------------------------------------------------
#define TM_C 64
#define KDIM_C 128
#define INS_C 132   // even -> 8B-aligned LDS.64 of (k, k+1)

__global__ __launch_bounds__(256)
void dense_kernel(const float4* __restrict__ side,
                  const float4* __restrict__ ego,
                  const float4* __restrict__ Wg, const float* __restrict__ bg,
                  const float4* __restrict__ Wb, const float* __restrict__ bb,
                  float4* __restrict__ out, int numTiles) {
    extern __shared__ float smem[];
    float* Wc2  = smem;                       // [64 kpair][64 col][2]
    float* In   = smem + KDIM_C * D_C;        // [64 row][132]
    float* bsum = In + TM_C * INS_C;          // [64]

    int tid = threadIdx.x;

#pragma unroll
    for (int i = 0; i < 8; i++) {
        int f = tid + i * 256;               // float4 index 0..2047
        int k = f >> 4, c4 = f & 15;
        float4 w = (k < 64) ? Wg[k * 16 + c4] : Wb[(k - 64) * 16 + c4];
        int kp = k >> 1, par = k & 1;
        float* dst = &Wc2[kp * 128 + (c4 * 4) * 2 + par];
        dst[0] = w.x; dst[2] = w.y; dst[4] = w.z; dst[6] = w.w;
    }
    if (tid < 64) bsum[tid] = bg[tid] + bb[tid];
    __syncthreads();

    int rg = tid >> 4;
    int cg = tid & 15;
    float4 bsv = *(float4*)&bsum[cg * 4];

    for (int tile = blockIdx.x; tile < numTiles; tile += gridDim.x) {
        int row0 = tile * TM_C;
        __syncthreads();

#pragma unroll
        for (int i = 0; i < 4; i++) {
            int f = tid + i * 256;
            int r = f >> 4, k4 = f & 15;
            float4 s  = make_float4(0.f, 0.f, 0.f, 0.f);
            float4 pr = make_float4(0.f, 0.f, 0.f, 0.f);
            int grow = row0 + r;
            if (grow < N_NODES_C) {
                s = side[grow * 16 + k4];
                float4 e = ego[grow * 16 + k4];
                pr = make_float4(s.x * e.x, s.y * e.y, s.z * e.z, s.w * e.w);
            }
            *(float4*)&In[r * INS_C + k4 * 4]      = s;
            *(float4*)&In[r * INS_C + 64 + k4 * 4] = pr;
        }
        __syncthreads();

        unsigned long long acc[4][4];
#pragma unroll
        for (int i = 0; i < 4; i++)
#pragma unroll
            for (int j = 0; j < 4; j++) acc[i][j] = 0ull;

        const float* Inr0 = &In[(rg * 4 + 0) * INS_C];
        const float* Inr1 = &In[(rg * 4 + 1) * INS_C];
        const float* Inr2 = &In[(rg * 4 + 2) * INS_C];
        const float* Inr3 = &In[(rg * 4 + 3) * INS_C];
        const unsigned long long* Wp = (const unsigned long long*)Wc2 + cg * 4;

#pragma unroll 4
        for (int kp = 0; kp < KDIM_C / 2; kp++) {
            unsigned long long a0 = *(const unsigned long long*)(Inr0 + 2 * kp);
            unsigned long long a1 = *(const unsigned long long*)(Inr1 + 2 * kp);
            unsigned long long a2 = *(const unsigned long long*)(Inr2 + 2 * kp);
            unsigned long long a3 = *(const unsigned long long*)(Inr3 + 2 * kp);
            ulonglong2 b01 = *(const ulonglong2*)(Wp + kp * 64);
            ulonglong2 b23 = *(const ulonglong2*)(Wp + kp * 64 + 2);
            acc[0][0] = fma2(a0, b01.x, acc[0][0]);
            acc[0][1] = fma2(a0, b01.y, acc[0][1]);
            acc[0][2] = fma2(a0, b23.x, acc[0][2]);
            acc[0][3] = fma2(a0, b23.y, acc[0][3]);
            acc[1][0] = fma2(a1, b01.x, acc[1][0]);
            acc[1][1] = fma2(a1, b01.y, acc[1][1]);
            acc[1][2] = fma2(a1, b23.x, acc[1][2]);
            acc[1][3] = fma2(a1, b23.y, acc[1][3]);
            acc[2][0] = fma2(a2, b01.x, acc[2][0]);
            acc[2][1] = fma2(a2, b01.y, acc[2][1]);
            acc[2][2] = fma2(a2, b23.x, acc[2][2]);
            acc[2][3] = fma2(a2, b23.y, acc[2][3]);
            acc[3][0] = fma2(a3, b01.x, acc[3][0]);
            acc[3][1] = fma2(a3, b01.y, acc[3][1]);
            acc[3][2] = fma2(a3, b23.x, acc[3][2]);
            acc[3][3] = fma2(a3, b23.y, acc[3][3]);
        }

#pragma unroll
        for (int i = 0; i < 4; i++) {
            float v0 = lo32(acc[i][0]) + hi32(acc[i][0]) + bsv.x;
            float v1 = lo32(acc[i][1]) + hi32(acc[i][1]) + bsv.y;
            float v2 = lo32(acc[i][2]) + hi32(acc[i][2]) + bsv.z;
            float v3 = lo32(acc[i][3]) + hi32(acc[i][3]) + bsv.w;
            v0 = (v0 > 0.f) ? v0 : 0.2f * v0;
            v1 = (v1 > 0.f) ? v1 : 0.2f * v1;
            v2 = (v2 > 0.f) ? v2 : 0.2f * v2;
            v3 = (v3 > 0.f) ? v3 : 0.2f * v3;
            float ss = v0 * v0 + v1 * v1 + v2 * v2 + v3 * v3;
#pragma unroll
            for (int o = 8; o > 0; o >>= 1)
                ss += __shfl_xor_sync(0xffffffffu, ss, o);
            float nrm = sqrtf(ss);
            float scl = 1.0f / fmaxf(nrm, 1e-12f);
            int grow = row0 + rg * 4 + i;
            if (grow < N_NODES_C)
                out[grow * 16 + cg] = make_float4(v0 * scl, v1 * scl, v2 * scl, v3 * scl);
        }
    }
}

// ---------------------------------------------------------------------------
// gamma[b] = sum over 3 embeddings of dot(emb[u], emb[N_USERS+item])
// ---------------------------------------------------------------------------
__global__ void gamma_kernel(const float* __restrict__ x,
                             const int* __restrict__ users,
                             const int* __restrict__ items,
                             float* __restrict__ out) {
    int b = blockIdx.x * 8 + (threadIdx.x >> 5);
    if (b >= BATCH_C) return;
    int lane = threadIdx.x & 31;
    int u  = users[b];
    int it = N_USERS_C + items[b];
    long long ub = (long long)u * D_C, ib = (long long)it * D_C;
    float acc = 0.f;
    acc += x[ub + lane]      * x[ib + lane];
    acc += x[ub + 32 + lane] * x[ib + 32 + lane];
    acc += g_ego1[ub + lane]      * g_ego1[ib + lane];
    acc += g_ego1[ub + 32 + lane] * g_ego1[ib + 32 + lane];
    acc += g_ego2[ub + lane]      * g_ego2[ib + lane];
    acc += g_ego2[ub + 32 + lane] * g_ego2[ib + 32 + lane];
#pragma unroll
    for (int o = 16; o > 0; o >>= 1)
        acc += __shfl_xor_sync(0xffffffffu, acc, o);
    if (lane == 0) out[b] = acc;
}

// ---------------------------------------------------------------------------
extern "C" void kernel_launch(void* const* d_in, const int* in_sizes, int n_in,
                              void* d_out, int out_size) {
    const int*   rows = (const int*)d_in[0];
    const int*   cols = (const int*)d_in[1];
    const float* vals = (const float*)d_in[2];
    const float* x    = (const float*)d_in[3];

    const float *Wg0, *bg0, *Wb0, *bb0, *Wg1, *bg1, *Wb1, *bb1;
    const int *users, *items;
    if (in_sizes[4] == BATCH_C) {
        users = (const int*)d_in[4];
        items = (const int*)d_in[5];
        Wg0 = (const float*)d_in[6];  bg0 = (const float*)d_in[7];
        Wb0 = (const float*)d_in[8];  bb0 = (const float*)d_in[9];
        Wg1 = (const float*)d_in[10]; bg1 = (const float*)d_in[11];
        Wb1 = (const float*)d_in[12]; bb1 = (const float*)d_in[13];
    } else {
        Wg0 = (const float*)d_in[4];  bg0 = (const float*)d_in[5];
        Wb0 = (const float*)d_in[6];  bb0 = (const float*)d_in[7];
        Wg1 = (const float*)d_in[8];  bg1 = (const float*)d_in[9];
        Wb1 = (const float*)d_in[10]; bb1 = (const float*)d_in[11];
        users = (const int*)d_in[12];
        items = (const int*)d_in[13];
    }

    float *side, *ego1, *ego2;
    int *cnt, *wpos, *bsum;
    int4 *epack;
    cudaGetSymbolAddress((void**)&side,  g_side);
    cudaGetSymbolAddress((void**)&ego1,  g_ego1);
    cudaGetSymbolAddress((void**)&ego2,  g_ego2);
    cudaGetSymbolAddress((void**)&cnt,   g_cnt);
    cudaGetSymbolAddress((void**)&wpos,  g_wpos);
    cudaGetSymbolAddress((void**)&bsum,  g_bsum);
    cudaGetSymbolAddress((void**)&epack, g_epack);

    int smemBytes = (KDIM_C * D_C + TM_C * INS_C + 64) * (int)sizeof(float);
    cudaFuncSetAttribute(dense_kernel, cudaFuncAttributeMaxDynamicSharedMemorySize, smemBytes);

    int numTiles   = (N_NODES_C + TM_C - 1) / TM_C;       // 2344
    int edgeBlocks = (NNZ_C + 255) / 256;                 // 9375
    int z4 = N_NODES_C * 16;
    int zeroBlocks = (z4 + 255) / 256;
    int spmmBlocks = NNZ_C / HEPB_C;                      // 9375

    // Build row-sorted edge list (shared by both layers)
    zero_cnt_kernel<<<NBLK_SCAN, SCB>>>(cnt);
    hist_kernel<<<edgeBlocks, 256>>>(rows, cnt);
    blocksum_kernel<<<NBLK_SCAN, SCB>>>(cnt, bsum);
    scan_bsum_kernel<<<1, 1024>>>(bsum);
    scan_final_kernel<<<NBLK_SCAN, SCB>>>(cnt, bsum, wpos);
    reorder_kernel<<<edgeBlocks, 256>>>(rows, cols, vals, wpos, epack);

    // Layer 1 (two D-half SpMM passes keep the random set L2-resident)
    zero_kernel<<<zeroBlocks, 256>>>((float4*)side, z4);
    seg_spmm_half_kernel<<<spmmBlocks, 256>>>(epack, (const float4*)x, (float4*)side, 0);
    seg_spmm_half_kernel<<<spmmBlocks, 256>>>(epack, (const float4*)x, (float4*)side, 8);
    dense_kernel<<<592, 256, smemBytes>>>((const float4*)side, (const float4*)x,
                                          (const float4*)Wg0, bg0,
                                          (const float4*)Wb0, bb0,
                                          (float4*)ego1, numTiles);
    // Layer 2
    zero_kernel<<<zeroBlocks, 256>>>((float4*)side, z4);
    seg_spmm_half_kernel<<<spmmBlocks, 256>>>(epack, (const float4*)ego1, (float4*)side, 0);
    seg_spmm_half_kernel<<<spmmBlocks, 256>>>(epack, (const float4*)ego1, (float4*)side, 8);
    dense_kernel<<<592, 256, smemBytes>>>((const float4*)side, (const float4*)ego1,
                                          (const float4*)Wg1, bg1,
                                          (const float4*)Wb1, bb1,
                                          (float4*)ego2, numTiles);
    // Final BPR scores
    gamma_kernel<<<BATCH_C / 8, 256>>>(x, users, items, (float*)d_out);
}

// round 10
// speedup vs baseline: 1.1838x; 1.0216x over previous
#include <cuda_runtime.h>
#include <cuda_fp16.h>
#include <math.h>
#include <stdint.h>

#define N_USERS_C 100000
#define N_ITEMS_C 50000
#define N_NODES_C 150000
#define D_C 64
#define NNZ_C 2400000
#define BATCH_C 2048
#define SCB 256
#define NBLK_SCAN ((N_NODES_C + SCB - 1) / SCB)   // 586

// Scratch buffers (allocation-free rule: device globals)
__device__ float g_side[N_NODES_C * D_C];
__device__ float g_ego1[N_NODES_C * D_C];
__device__ float g_ego2[N_NODES_C * D_C];
__device__ uint2 g_egoh[N_NODES_C * 16];  // fp16 copy of current ego (4 halves per uint2)
__device__ int   g_cnt[N_NODES_C];
__device__ int   g_wpos[N_NODES_C];
__device__ int   g_bsum[1024];
__device__ int4  g_epack[NNZ_C];          // (row, col, val-bits, 0) grouped by row

// Packed fp32x2 FMA (sm_103a): lo/hi lanes independent fp32 FMAs
__device__ __forceinline__ unsigned long long fma2(unsigned long long a,
                                                   unsigned long long b,
                                                   unsigned long long c) {
    unsigned long long d;
    asm("fma.rn.f32x2 %0, %1, %2, %3;" : "=l"(d) : "l"(a), "l"(b), "l"(c));
    return d;
}
__device__ __forceinline__ float lo32(unsigned long long v) {
    return __uint_as_float((unsigned)(v & 0xffffffffull));
}
__device__ __forceinline__ float hi32(unsigned long long v) {
    return __uint_as_float((unsigned)(v >> 32));
}

// ---------------------------------------------------------------------------
// CSR-order build: zero counts -> histogram -> hierarchical scan -> reorder
// ---------------------------------------------------------------------------
__global__ void zero_cnt_kernel(int* __restrict__ cnt) {
    int i = blockIdx.x * blockDim.x + threadIdx.x;
    if (i < N_NODES_C) cnt[i] = 0;
}

__global__ void hist_kernel(const int* __restrict__ rows, int* __restrict__ cnt) {
    int e = blockIdx.x * blockDim.x + threadIdx.x;
    if (e < NNZ_C) atomicAdd(&cnt[rows[e]], 1);
}

__global__ void blocksum_kernel(const int* __restrict__ cnt, int* __restrict__ bsum) {
    __shared__ int s[SCB];
    int i = blockIdx.x * SCB + threadIdx.x;
    s[threadIdx.x] = (i < N_NODES_C) ? cnt[i] : 0;
    __syncthreads();
#pragma unroll
    for (int o = SCB / 2; o > 0; o >>= 1) {
        if (threadIdx.x < o) s[threadIdx.x] += s[threadIdx.x + o];
        __syncthreads();
    }
    if (threadIdx.x == 0) bsum[blockIdx.x] = s[0];
}

__global__ __launch_bounds__(1024)
void scan_bsum_kernel(int* __restrict__ bsum) {
    __shared__ int s[1024];
    int tid = threadIdx.x;
    int v = (tid < NBLK_SCAN) ? bsum[tid] : 0;
    s[tid] = v;
    __syncthreads();
    for (int o = 1; o < 1024; o <<= 1) {
        int a = (tid >= o) ? s[tid - o] : 0;
        __syncthreads();
        s[tid] += a;
        __syncthreads();
    }
    if (tid < NBLK_SCAN) bsum[tid] = s[tid] - v;   // exclusive
}

__global__ void scan_final_kernel(const int* __restrict__ cnt,
                                  const int* __restrict__ bsum,
                                  int* __restrict__ wpos) {
    __shared__ int s[SCB];
    int i = blockIdx.x * SCB + threadIdx.x;
    int v = (i < N_NODES_C) ? cnt[i] : 0;
    s[threadIdx.x] = v;
    __syncthreads();
    for (int o = 1; o < SCB; o <<= 1) {
        int a = (threadIdx.x >= o) ? s[threadIdx.x - o] : 0;
        __syncthreads();
        s[threadIdx.x] += a;
        __syncthreads();
    }
    if (i < N_NODES_C) wpos[i] = bsum[blockIdx.x] + s[threadIdx.x] - v;
}

__global__ void reorder_kernel(const int* __restrict__ rows,
                               const int* __restrict__ cols,
                               const float* __restrict__ vals,
                               int* __restrict__ wpos,
                               int4* __restrict__ epack) {
    int e = blockIdx.x * blockDim.x + threadIdx.x;
    if (e >= NNZ_C) return;
    int r = rows[e];
    int p = atomicAdd(&wpos[r], 1);
    epack[p] = make_int4(r, cols[e], __float_as_int(vals[e]), 0);
}

// ---------------------------------------------------------------------------
// zero: clear the scatter accumulator
// ---------------------------------------------------------------------------
__global__ void zero_kernel(float4* __restrict__ p, int n4) {
    int i = blockIdx.x * blockDim.x + threadIdx.x;
    if (i < n4) p[i] = make_float4(0.f, 0.f, 0.f, 0.f);
}

// ---------------------------------------------------------------------------
// fp32 -> fp16 conversion (streaming): ego (float4) -> egoh (4 halves / uint2)
// ---------------------------------------------------------------------------
__global__ void f2h_kernel(const float4* __restrict__ in, uint2* __restrict__ out, int n4) {
    int i = blockIdx.x * blockDim.x + threadIdx.x;
    if (i >= n4) return;
    float4 v = in[i];
    __half2 a = __floats2half2_rn(v.x, v.y);
    __half2 b = __floats2half2_rn(v.z, v.w);
    uint2 o;
    o.x = *reinterpret_cast<unsigned*>(&a);
    o.y = *reinterpret_cast<unsigned*>(&b);
    out[i] = o;
}

// ---------------------------------------------------------------------------
// Segmented SpMM over row-sorted edges, fp16-gather edition.
// Random-read array is the 19.2MB fp16 ego copy -> fully L2-resident, single
// full-D pass. 16 slots x 16 edges per block; each lane owns one edge load
// (coalesced) and a 4-dim slice (uint2 = 4 halves, 128B/edge warp-coalesced).
// fp32 accumulate + fp32 vector-RED flush on row change. NNZ = 9375*256.
// ---------------------------------------------------------------------------
#define EPS_C 16   // edges per slot
#define EPB_C 256  // edges per block

__device__ __forceinline__ void red_v4(float4* dst, float4 a) {
    asm volatile("red.global.add.v4.f32 [%0], {%1, %2, %3, %4};"
                 :: "l"(dst), "f"(a.x), "f"(a.y), "f"(a.z), "f"(a.w)
                 : "memory");
}

__global__ __launch_bounds__(256)
void seg_spmm_h_kernel(const int4* __restrict__ epack,
                       const uint2* __restrict__ egoh,
                       float4* __restrict__ side) {
    int tid  = threadIdx.x;
    int slot = tid >> 4;                   // 0..15
    int lane = tid & 15;                   // 4-dim slice of the 64-dim row
    int half = (tid & 31) >= 16 ? 16 : 0;  // shfl base of this slot in the warp
    int e0 = blockIdx.x * EPB_C + slot * EPS_C;

    // Each lane owns one edge of its slot: 16 consecutive int4 -> coalesced
    int4 ep = epack[e0 + lane];

    float4 acc = make_float4(0.f, 0.f, 0.f, 0.f);
    int cur = -1;

#pragma unroll
    for (int b = 0; b < 4; b++) {
        int rr[4]; float vv[4]; uint2 gh[4];
#pragma unroll
        for (int u = 0; u < 4; u++) {
            int src = half + b * 4 + u;
            int c  = __shfl_sync(0xffffffffu, ep.y, src);
            rr[u]  = __shfl_sync(0xffffffffu, ep.x, src);
            vv[u]  = __int_as_float(__shfl_sync(0xffffffffu, ep.z, src));
            gh[u]  = egoh[c * 16 + lane];   // 8B/lane, 128B coalesced per edge
        }
#pragma unroll
        for (int u = 0; u < 4; u++) {
            if (rr[u] != cur) {
                if (cur >= 0) red_v4(&side[cur * 16 + lane], acc);
                acc = make_float4(0.f, 0.f, 0.f, 0.f);
                cur = rr[u];
            }
            __half2 h01 = *reinterpret_cast<__half2*>(&gh[u].x);
            __half2 h23 = *reinterpret_cast<__half2*>(&gh[u].y);
            float2 f01 = __half22float2(h01);
            float2 f23 = __half22float2(h23);
            acc.x = fmaf(vv[u], f01.x, acc.x);
            acc.y = fmaf(vv[u], f01.y, acc.y);
            acc.z = fmaf(vv[u], f23.x, acc.z);
            acc.w = fmaf(vv[u], f23.y, acc.w);
        }
    }
    if (cur >= 0)
        red_v4(&side[cur * 16 + lane], acc);
}

// ---------------------------------------------------------------------------
// Dense layer via packed FFMA2 (exact fp32 math):
// out = l2norm(leaky_relu(side@Wg + (ego*side)@Wb + bg + bb))
// ---------------------------------------------------------------------------
#define TM_C 64
#define KDIM_C 128
#define INS_C 132   // even -> 8B-aligned LDS.64 of (k, k+1)

__global__ __launch_bounds__(256)
void dense_kernel(const float4* __restrict__ side,
                  const float4* __restrict__ ego,
                  const float4* __restrict__ Wg, const float* __restrict__ bg,
                  const float4* __restrict__ Wb, const float* __restrict__ bb,
                  float4* __restrict__ out, int numTiles) {
    extern __shared__ float smem[];
    float* Wc2  = smem;                       // [64 kpair][64 col][2]
    float* In   = smem + KDIM_C * D_C;        // [64 row][132]
    float* bsum = In + TM_C * INS_C;          // [64]

    int tid = threadIdx.x;

#pragma unroll
    for (int i = 0; i < 8; i++) {
        int f = tid + i * 256;               // float4 index 0..2047
        int k = f >> 4, c4 = f & 15;
        float4 w = (k < 64) ? Wg[k * 16 + c4] : Wb[(k - 64) * 16 + c4];
        int kp = k >> 1, par = k & 1;
        float* dst = &Wc2[kp * 128 + (c4 * 4) * 2 + par];
        dst[0] = w.x; dst[2] = w.y; dst[4] = w.z; dst[6] = w.w;
    }
    if (tid < 64) bsum[tid] = bg[tid] + bb[tid];
    __syncthreads();

    int rg = tid >> 4;
    int cg = tid & 15;
    float4 bsv = *(float4*)&bsum[cg * 4];

    for (int tile = blockIdx.x; tile < numTiles; tile += gridDim.x) {
        int row0 = tile * TM_C;
        __syncthreads();

#pragma unroll
        for (int i = 0; i < 4; i++) {
            int f = tid + i * 256;
            int r = f >> 4, k4 = f & 15;
            float4 s  = make_float4(0.f, 0.f, 0.f, 0.f);
            float4 pr = make_float4(0.f, 0.f, 0.f, 0.f);
            int grow = row0 + r;
            if (grow < N_NODES_C) {
                s = side[grow * 16 + k4];
                float4 e = ego[grow * 16 + k4];
                pr = make_float4(s.x * e.x, s.y * e.y, s.z * e.z, s.w * e.w);
            }
            *(float4*)&In[r * INS_C + k4 * 4]      = s;
            *(float4*)&In[r * INS_C + 64 + k4 * 4] = pr;
        }
        __syncthreads();

        unsigned long long acc[4][4];
#pragma unroll
        for (int i = 0; i < 4; i++)
#pragma unroll
            for (int j = 0; j < 4; j++) acc[i][j] = 0ull;

        const float* Inr0 = &In[(rg * 4 + 0) * INS_C];
        const float* Inr1 = &In[(rg * 4 + 1) * INS_C];
        const float* Inr2 = &In[(rg * 4 + 2) * INS_C];
        const float* Inr3 = &In[(rg * 4 + 3) * INS_C];
        const unsigned long long* Wp = (const unsigned long long*)Wc2 + cg * 4;

#pragma unroll 4
        for (int kp = 0; kp < KDIM_C / 2; kp++) {
            unsigned long long a0 = *(const unsigned long long*)(Inr0 + 2 * kp);
            unsigned long long a1 = *(const unsigned long long*)(Inr1 + 2 * kp);
            unsigned long long a2 = *(const unsigned long long*)(Inr2 + 2 * kp);
            unsigned long long a3 = *(const unsigned long long*)(Inr3 + 2 * kp);
            ulonglong2 b01 = *(const ulonglong2*)(Wp + kp * 64);
            ulonglong2 b23 = *(const ulonglong2*)(Wp + kp * 64 + 2);
            acc[0][0] = fma2(a0, b01.x, acc[0][0]);
            acc[0][1] = fma2(a0, b01.y, acc[0][1]);
            acc[0][2] = fma2(a0, b23.x, acc[0][2]);
            acc[0][3] = fma2(a0, b23.y, acc[0][3]);
            acc[1][0] = fma2(a1, b01.x, acc[1][0]);
            acc[1][1] = fma2(a1, b01.y, acc[1][1]);
            acc[1][2] = fma2(a1, b23.x, acc[1][2]);
            acc[1][3] = fma2(a1, b23.y, acc[1][3]);
            acc[2][0] = fma2(a2, b01.x, acc[2][0]);
            acc[2][1] = fma2(a2, b01.y, acc[2][1]);
            acc[2][2] = fma2(a2, b23.x, acc[2][2]);
            acc[2][3] = fma2(a2, b23.y, acc[2][3]);
            acc[3][0] = fma2(a3, b01.x, acc[3][0]);
            acc[3][1] = fma2(a3, b01.y, acc[3][1]);
            acc[3][2] = fma2(a3, b23.x, acc[3][2]);
            acc[3][3] = fma2(a3, b23.y, acc[3][3]);
        }

#pragma unroll
        for (int i = 0; i < 4; i++) {
            float v0 = lo32(acc[i][0]) + hi32(acc[i][0]) + bsv.x;
            float v1 = lo32(acc[i][1]) + hi32(acc[i][1]) + bsv.y;
            float v2 = lo32(acc[i][2]) + hi32(acc[i][2]) + bsv.z;
            float v3 = lo32(acc[i][3]) + hi32(acc[i][3]) + bsv.w;
            v0 = (v0 > 0.f) ? v0 : 0.2f * v0;
            v1 = (v1 > 0.f) ? v1 : 0.2f * v1;
            v2 = (v2 > 0.f) ? v2 : 0.2f * v2;
            v3 = (v3 > 0.f) ? v3 : 0.2f * v3;
            float ss = v0 * v0 + v1 * v1 + v2 * v2 + v3 * v3;
#pragma unroll
            for (int o = 8; o > 0; o >>= 1)
                ss += __shfl_xor_sync(0xffffffffu, ss, o);
            float nrm = sqrtf(ss);
            float scl = 1.0f / fmaxf(nrm, 1e-12f);
            int grow = row0 + rg * 4 + i;
            if (grow < N_NODES_C)
                out[grow * 16 + cg] = make_float4(v0 * scl, v1 * scl, v2 * scl, v3 * scl);
        }
    }
}

// ---------------------------------------------------------------------------
// gamma[b] = sum over 3 embeddings of dot(emb[u], emb[N_USERS+item])
// ---------------------------------------------------------------------------
__global__ void gamma_kernel(const float* __restrict__ x,
                             const int* __restrict__ users,
                             const int* __restrict__ items,
                             float* __restrict__ out) {
    int b = blockIdx.x * 8 + (threadIdx.x >> 5);
    if (b >= BATCH_C) return;
    int lane = threadIdx.x & 31;
    int u  = users[b];
    int it = N_USERS_C + items[b];
    long long ub = (long long)u * D_C, ib = (long long)it * D_C;
    float acc = 0.f;
    acc += x[ub + lane]      * x[ib + lane];
    acc += x[ub + 32 + lane] * x[ib + 32 + lane];
    acc += g_ego1[ub + lane]      * g_ego1[ib + lane];
    acc += g_ego1[ub + 32 + lane] * g_ego1[ib + 32 + lane];
    acc += g_ego2[ub + lane]      * g_ego2[ib + lane];
    acc += g_ego2[ub + 32 + lane] * g_ego2[ib + 32 + lane];
#pragma unroll
    for (int o = 16; o > 0; o >>= 1)
        acc += __shfl_xor_sync(0xffffffffu, acc, o);
    if (lane == 0) out[b] = acc;
}

// ---------------------------------------------------------------------------
extern "C" void kernel_launch(void* const* d_in, const int* in_sizes, int n_in,
                              void* d_out, int out_size) {
    const int*   rows = (const int*)d_in[0];
    const int*   cols = (const int*)d_in[1];
    const float* vals = (const float*)d_in[2];
    const float* x    = (const float*)d_in[3];

    const float *Wg0, *bg0, *Wb0, *bb0, *Wg1, *bg1, *Wb1, *bb1;
    const int *users, *items;
    if (in_sizes[4] == BATCH_C) {
        users = (const int*)d_in[4];
        items = (const int*)d_in[5];
        Wg0 = (const float*)d_in[6];  bg0 = (const float*)d_in[7];
        Wb0 = (const float*)d_in[8];  bb0 = (const float*)d_in[9];
        Wg1 = (const float*)d_in[10]; bg1 = (const float*)d_in[11];
        Wb1 = (const float*)d_in[12]; bb1 = (const float*)d_in[13];
    } else {
        Wg0 = (const float*)d_in[4];  bg0 = (const float*)d_in[5];
        Wb0 = (const float*)d_in[6];  bb0 = (const float*)d_in[7];
        Wg1 = (const float*)d_in[8];  bg1 = (const float*)d_in[9];
        Wb1 = (const float*)d_in[10]; bb1 = (const float*)d_in[11];
        users = (const int*)d_in[12];
        items = (const int*)d_in[13];
    }

    float *side, *ego1, *ego2;
    uint2 *egoh;
    int *cnt, *wpos, *bsum;
    int4 *epack;
    cudaGetSymbolAddress((void**)&side,  g_side);
    cudaGetSymbolAddress((void**)&ego1,  g_ego1);
    cudaGetSymbolAddress((void**)&ego2,  g_ego2);
    cudaGetSymbolAddress((void**)&egoh,  g_egoh);
    cudaGetSymbolAddress((void**)&cnt,   g_cnt);
    cudaGetSymbolAddress((void**)&wpos,  g_wpos);
    cudaGetSymbolAddress((void**)&bsum,  g_bsum);
    cudaGetSymbolAddress((void**)&epack, g_epack);

    int smemBytes = (KDIM_C * D_C + TM_C * INS_C + 64) * (int)sizeof(float);
    cudaFuncSetAttribute(dense_kernel, cudaFuncAttributeMaxDynamicSharedMemorySize, smemBytes);

    int numTiles   = (N_NODES_C + TM_C - 1) / TM_C;       // 2344
    int edgeBlocks = (NNZ_C + 255) / 256;                 // 9375
    int z4 = N_NODES_C * 16;
    int zeroBlocks = (z4 + 255) / 256;
    int spmmBlocks = NNZ_C / EPB_C;                       // 9375

    // Build row-sorted edge list (shared by both layers)
    zero_cnt_kernel<<<NBLK_SCAN, SCB>>>(cnt);
    hist_kernel<<<edgeBlocks, 256>>>(rows, cnt);
    blocksum_kernel<<<NBLK_SCAN, SCB>>>(cnt, bsum);
    scan_bsum_kernel<<<1, 1024>>>(bsum);
    scan_final_kernel<<<NBLK_SCAN, SCB>>>(cnt, bsum, wpos);
    reorder_kernel<<<edgeBlocks, 256>>>(rows, cols, vals, wpos, epack);

    // Layer 1: fp16 gather copy of x, L2-resident single-pass SpMM
    f2h_kernel<<<zeroBlocks, 256>>>((const float4*)x, egoh, z4);
    zero_kernel<<<zeroBlocks, 256>>>((float4*)side, z4);
    seg_spmm_h_kernel<<<spmmBlocks, 256>>>(epack, egoh, (float4*)side);
    dense_kernel<<<592, 256, smemBytes>>>((const float4*)side, (const float4*)x,
                                          (const float4*)Wg0, bg0,
                                          (const float4*)Wb0, bb0,
                                          (float4*)ego1, numTiles);
    // Layer 2
    f2h_kernel<<<zeroBlocks, 256>>>((const float4*)ego1, egoh, z4);
    zero_kernel<<<zeroBlocks, 256>>>((float4*)side, z4);
    seg_spmm_h_kernel<<<spmmBlocks, 256>>>(epack, egoh, (float4*)side);
    dense_kernel<<<592, 256, smemBytes>>>((const float4*)side, (const float4*)ego1,
                                          (const float4*)Wg1, bg1,
                                          (const float4*)Wb1, bb1,
                                          (float4*)ego2, numTiles);
    // Final BPR scores
    gamma_kernel<<<BATCH_C / 8, 256>>>(x, users, items, (float*)d_out);
}

// round 11
// speedup vs baseline: 1.1878x; 1.0034x over previous
#include <cuda_runtime.h>
#include <cuda_fp16.h>
#include <math.h>
#include <stdint.h>

#define N_USERS_C 100000
#define N_ITEMS_C 50000
#define N_NODES_C 150000
#define D_C 64
#define NNZ_C 2400000
#define BATCH_C 2048
#define SCB 256
#define NBLK_SCAN ((N_NODES_C + SCB - 1) / SCB)   // 586

// Scratch buffers (allocation-free rule: device globals)
__device__ float g_side[N_NODES_C * D_C];
__device__ float g_ego1[N_NODES_C * D_C];
__device__ float g_ego2[N_NODES_C * D_C];
__device__ uint2 g_egoh[N_NODES_C * 16];  // fp16 copy of current ego
__device__ int   g_cnt[N_NODES_C];
__device__ int   g_wpos[N_NODES_C];
__device__ int   g_agg[1024];
__device__ int   g_flag[1024];
__device__ int2  g_epack[NNZ_C];          // packed (row18,col18,val16) by row

// Packed fp32x2 FMA (sm_103a)
__device__ __forceinline__ unsigned long long fma2(unsigned long long a,
                                                   unsigned long long b,
                                                   unsigned long long c) {
    unsigned long long d;
    asm("fma.rn.f32x2 %0, %1, %2, %3;" : "=l"(d) : "l"(a), "l"(b), "l"(c));
    return d;
}
__device__ __forceinline__ float lo32(unsigned long long v) {
    return __uint_as_float((unsigned)(v & 0xffffffffull));
}
__device__ __forceinline__ float hi32(unsigned long long v) {
    return __uint_as_float((unsigned)(v >> 32));
}

// ---------------------------------------------------------------------------
// pre: zero cnt + side accumulator + scan flags (one streaming kernel)
// ---------------------------------------------------------------------------
__global__ void pre_kernel(int* __restrict__ cnt, float4* __restrict__ side,
                           int* __restrict__ flag, int n4) {
    int i = blockIdx.x * blockDim.x + threadIdx.x;
    if (i < n4) side[i] = make_float4(0.f, 0.f, 0.f, 0.f);
    if (i < N_NODES_C) cnt[i] = 0;
    if (i < 1024) flag[i] = 0;
}

// ---------------------------------------------------------------------------
// fp32 -> fp16 conversion (streaming); optional side zeroing fused
// ---------------------------------------------------------------------------
__global__ void f2h_kernel(const float4* __restrict__ in, uint2* __restrict__ out, int n4) {
    int i = blockIdx.x * blockDim.x + threadIdx.x;
    if (i >= n4) return;
    float4 v = in[i];
    __half2 a = __floats2half2_rn(v.x, v.y);
    __half2 b = __floats2half2_rn(v.z, v.w);
    uint2 o;
    o.x = *reinterpret_cast<unsigned*>(&a);
    o.y = *reinterpret_cast<unsigned*>(&b);
    out[i] = o;
}

__global__ void f2h_zero_kernel(const float4* __restrict__ in, uint2* __restrict__ out,
                                float4* __restrict__ side, int n4) {
    int i = blockIdx.x * blockDim.x + threadIdx.x;
    if (i >= n4) return;
    float4 v = in[i];
    __half2 a = __floats2half2_rn(v.x, v.y);
    __half2 b = __floats2half2_rn(v.z, v.w);
    uint2 o;
    o.x = *reinterpret_cast<unsigned*>(&a);
    o.y = *reinterpret_cast<unsigned*>(&b);
    out[i] = o;
    side[i] = make_float4(0.f, 0.f, 0.f, 0.f);
}

// ---------------------------------------------------------------------------
// Histogram of row degrees
// ---------------------------------------------------------------------------
__global__ void hist_kernel(const int* __restrict__ rows, int* __restrict__ cnt) {
    int e = blockIdx.x * blockDim.x + threadIdx.x;
    if (e < NNZ_C) atomicAdd(&cnt[rows[e]], 1);
}

// ---------------------------------------------------------------------------
// Single-pass scan with decoupled aggregates: every block publishes its sum,
// then sums all predecessor aggregates itself. All 586 blocks co-resident.
// ---------------------------------------------------------------------------
__global__ __launch_bounds__(SCB)
void scan_fused_kernel(const int* __restrict__ cnt, int* __restrict__ wpos,
                       int* __restrict__ agg, int* __restrict__ flag) {
    __shared__ int s[SCB];
    __shared__ int prefixSh;
    int b = blockIdx.x;
    int tid = threadIdx.x;
    int i = b * SCB + tid;
    int v = (i < N_NODES_C) ? cnt[i] : 0;
    s[tid] = v;
    __syncthreads();
    // inclusive Hillis-Steele
    for (int o = 1; o < SCB; o <<= 1) {
        int a = (tid >= o) ? s[tid - o] : 0;
        __syncthreads();
        s[tid] += a;
        __syncthreads();
    }
    int incl = s[tid];
    if (tid == SCB - 1) {
        agg[b] = incl;          // block total
        __threadfence();
        flag[b] = 1;
    }
    // warp 0 gathers predecessor aggregates
    if (tid < 32) {
        int sum = 0;
        for (int j = tid; j < b; j += 32) {
            while (((volatile int*)flag)[j] == 0) {}
            sum += ((volatile int*)agg)[j];
        }
#pragma unroll
        for (int o = 16; o > 0; o >>= 1)
            sum += __shfl_xor_sync(0xffffffffu, sum, o);
        if (tid == 0) prefixSh = sum;
    }
    __syncthreads();
    if (i < N_NODES_C) wpos[i] = prefixSh + incl - v;   // exclusive prefix
}

// ---------------------------------------------------------------------------
// Reorder into row-grouped packed int2: w0 = col | rowLow14<<18,
// w1 = rowHigh4 | val_fp16<<16
// ---------------------------------------------------------------------------
__global__ void reorder_kernel(const int* __restrict__ rows,
                               const int* __restrict__ cols,
                               const float* __restrict__ vals,
                               int* __restrict__ wpos,
                               int2* __restrict__ epack) {
    int e = blockIdx.x * blockDim.x + threadIdx.x;
    if (e >= NNZ_C) return;
    int r = rows[e];
    int p = atomicAdd(&wpos[r], 1);
    unsigned short hv = __half_as_ushort(__float2half_rn(vals[e]));
    int w0 = cols[e] | ((r & 0x3FFF) << 18);
    int w1 = (r >> 14) | ((int)hv << 16);
    epack[p] = make_int2(w0, w1);
}

// ---------------------------------------------------------------------------
// Segmented SpMM over row-sorted packed edges, fp16 gather.
// 16 slots x 16 edges per block; lane owns one 8B edge load + a 4-dim slice.
// fp32 accumulate, vector-RED flush on row change. NNZ = 9375*256.
// ---------------------------------------------------------------------------
#define EPS_C 16
#define EPB_C 256

__device__ __forceinline__ void red_v4(float4* dst, float4 a) {
    asm volatile("red.global.add.v4.f32 [%0], {%1, %2, %3, %4};"
                 :: "l"(dst), "f"(a.x), "f"(a.y), "f"(a.z), "f"(a.w)
                 : "memory");
}

__global__ __launch_bounds__(256)
void seg_spmm_h_kernel(const int2* __restrict__ epack,
                       const uint2* __restrict__ egoh,
                       float4* __restrict__ side) {
    int tid  = threadIdx.x;
    int slot = tid >> 4;                   // 0..15
    int lane = tid & 15;                   // 4-dim slice of the 64-dim row
    int half = (tid & 31) >= 16 ? 16 : 0;  // shfl base of this slot in the warp
    int e0 = blockIdx.x * EPB_C + slot * EPS_C;

    int2 ep = epack[e0 + lane];            // coalesced 128B per slot

    float4 acc = make_float4(0.f, 0.f, 0.f, 0.f);
    int cur = -1;

#pragma unroll
    for (int b = 0; b < 4; b++) {
        int rr[4]; float vv[4]; uint2 gh[4];
#pragma unroll
        for (int u = 0; u < 4; u++) {
            int src = half + b * 4 + u;
            int w0 = __shfl_sync(0xffffffffu, ep.x, src);
            int w1 = __shfl_sync(0xffffffffu, ep.y, src);
            int c  = w0 & 0x3FFFF;
            rr[u]  = ((w0 >> 18) & 0x3FFF) | ((w1 & 0xF) << 14);
            vv[u]  = __half2float(__ushort_as_half((unsigned short)((unsigned)w1 >> 16)));
            gh[u]  = egoh[c * 16 + lane];
        }
#pragma unroll
        for (int u = 0; u < 4; u++) {
            if (rr[u] != cur) {
                if (cur >= 0) red_v4(&side[cur * 16 + lane], acc);
                acc = make_float4(0.f, 0.f, 0.f, 0.f);
                cur = rr[u];
            }
            __half2 h01 = *reinterpret_cast<__half2*>(&gh[u].x);
            __half2 h23 = *reinterpret_cast<__half2*>(&gh[u].y);
            float2 f01 = __half22float2(h01);
            float2 f23 = __half22float2(h23);
            acc.x = fmaf(vv[u], f01.x, acc.x);
            acc.y = fmaf(vv[u], f01.y, acc.y);
            acc.z = fmaf(vv[u], f23.x, acc.z);
            acc.w = fmaf(vv[u], f23.y, acc.w);
        }
    }
    if (cur >= 0)
        red_v4(&side[cur * 16 + lane], acc);
}

// ---------------------------------------------------------------------------
// Dense layer via packed FFMA2 (exact fp32 math):
// out = l2norm(leaky_relu(side@Wg + (ego*side)@Wb + bg + bb))
// ---------------------------------------------------------------------------
#define TM_C 64
#define KDIM_C 128
#define INS_C 132

__global__ __launch_bounds__(256)
void dense_kernel(const float4* __restrict__ side,
                  const float4* __restrict__ ego,
                  const float4* __restrict__ Wg, const float* __restrict__ bg,
                  const float4* __restrict__ Wb, const float* __restrict__ bb,
                  float4* __restrict__ out, int numTiles) {
    extern __shared__ float smem[];
    float* Wc2  = smem;                       // [64 kpair][64 col][2]
    float* In   = smem + KDIM_C * D_C;        // [64 row][132]
    float* bsum = In + TM_C * INS_C;          // [64]

    int tid = threadIdx.x;

#pragma unroll
    for (int i = 0; i < 8; i++) {
        int f = tid + i * 256;
        int k = f >> 4, c4 = f & 15;
        float4 w = (k < 64) ? Wg[k * 16 + c4] : Wb[(k - 64) * 16 + c4];
        int kp = k >> 1, par = k & 1;
        float* dst = &Wc2[kp * 128 + (c4 * 4) * 2 + par];
        dst[0] = w.x; dst[2] = w.y; dst[4] = w.z; dst[6] = w.w;
    }
    if (tid < 64) bsum[tid] = bg[tid] + bb[tid];
    __syncthreads();

    int rg = tid >> 4;
    int cg = tid & 15;
    float4 bsv = *(float4*)&bsum[cg * 4];

    for (int tile = blockIdx.x; tile < numTiles; tile += gridDim.x) {
        int row0 = tile * TM_C;
        __syncthreads();

#pragma unroll
        for (int i = 0; i < 4; i++) {
            int f = tid + i * 256;
            int r = f >> 4, k4 = f & 15;
            float4 s  = make_float4(0.f, 0.f, 0.f, 0.f);
            float4 pr = make_float4(0.f, 0.f, 0.f, 0.f);
            int grow = row0 + r;
            if (grow < N_NODES_C) {
                s = side[grow * 16 + k4];
                float4 e = ego[grow * 16 + k4];
                pr = make_float4(s.x * e.x, s.y * e.y, s.z * e.z, s.w * e.w);
            }
            *(float4*)&In[r * INS_C + k4 * 4]      = s;
            *(float4*)&In[r * INS_C + 64 + k4 * 4] = pr;
        }
        __syncthreads();

        unsigned long long acc[4][4];
#pragma unroll
        for (int i = 0; i < 4; i++)
#pragma unroll
            for (int j = 0; j < 4; j++) acc[i][j] = 0ull;

        const float* Inr0 = &In[(rg * 4 + 0) * INS_C];
        const float* Inr1 = &In[(rg * 4 + 1) * INS_C];
        const float* Inr2 = &In[(rg * 4 + 2) * INS_C];
        const float* Inr3 = &In[(rg * 4 + 3) * INS_C];
        const unsigned long long* Wp = (const unsigned long long*)Wc2 + cg * 4;

#pragma unroll 4
        for (int kp = 0; kp < KDIM_C / 2; kp++) {
            unsigned long long a0 = *(const unsigned long long*)(Inr0 + 2 * kp);
            unsigned long long a1 = *(const unsigned long long*)(Inr1 + 2 * kp);
            unsigned long long a2 = *(const unsigned long long*)(Inr2 + 2 * kp);
            unsigned long long a3 = *(const unsigned long long*)(Inr3 + 2 * kp);
            ulonglong2 b01 = *(const ulonglong2*)(Wp + kp * 64);
            ulonglong2 b23 = *(const ulonglong2*)(Wp + kp * 64 + 2);
            acc[0][0] = fma2(a0, b01.x, acc[0][0]);
            acc[0][1] = fma2(a0, b01.y, acc[0][1]);
            acc[0][2] = fma2(a0, b23.x, acc[0][2]);
            acc[0][3] = fma2(a0, b23.y, acc[0][3]);
            acc[1][0] = fma2(a1, b01.x, acc[1][0]);
            acc[1][1] = fma2(a1, b01.y, acc[1][1]);
            acc[1][2] = fma2(a1, b23.x, acc[1][2]);
            acc[1][3] = fma2(a1, b23.y, acc[1][3]);
            acc[2][0] = fma2(a2, b01.x, acc[2][0]);
            acc[2][1] = fma2(a2, b01.y, acc[2][1]);
            acc[2][2] = fma2(a2, b23.x, acc[2][2]);
            acc[2][3] = fma2(a2, b23.y, acc[2][3]);
            acc[3][0] = fma2(a3, b01.x, acc[3][0]);
            acc[3][1] = fma2(a3, b01.y, acc[3][1]);
            acc[3][2] = fma2(a3, b23.x, acc[3][2]);
            acc[3][3] = fma2(a3, b23.y, acc[3][3]);
        }

#pragma unroll
        for (int i = 0; i < 4; i++) {
            float v0 = lo32(acc[i][0]) + hi32(acc[i][0]) + bsv.x;
            float v1 = lo32(acc[i][1]) + hi32(acc[i][1]) + bsv.y;
            float v2 = lo32(acc[i][2]) + hi32(acc[i][2]) + bsv.z;
            float v3 = lo32(acc[i][3]) + hi32(acc[i][3]) + bsv.w;
            v0 = (v0 > 0.f) ? v0 : 0.2f * v0;
            v1 = (v1 > 0.f) ? v1 : 0.2f * v1;
            v2 = (v2 > 0.f) ? v2 : 0.2f * v2;
            v3 = (v3 > 0.f) ? v3 : 0.2f * v3;
            float ss = v0 * v0 + v1 * v1 + v2 * v2 + v3 * v3;
#pragma unroll
            for (int o = 8; o > 0; o >>= 1)
                ss += __shfl_xor_sync(0xffffffffu, ss, o);
            float nrm = sqrtf(ss);
            float scl = 1.0f / fmaxf(nrm, 1e-12f);
            int grow = row0 + rg * 4 + i;
            if (grow < N_NODES_C)
                out[grow * 16 + cg] = make_float4(v0 * scl, v1 * scl, v2 * scl, v3 * scl);
        }
    }
}

// ---------------------------------------------------------------------------
// gamma[b] = sum over 3 embeddings of dot(emb[u], emb[N_USERS+item])
// ---------------------------------------------------------------------------
__global__ void gamma_kernel(const float* __restrict__ x,
                             const int* __restrict__ users,
                             const int* __restrict__ items,
                             float* __restrict__ out) {
    int b = blockIdx.x * 8 + (threadIdx.x >> 5);
    if (b >= BATCH_C) return;
    int lane = threadIdx.x & 31;
    int u  = users[b];
    int it = N_USERS_C + items[b];
    long long ub = (long long)u * D_C, ib = (long long)it * D_C;
    float acc = 0.f;
    acc += x[ub + lane]      * x[ib + lane];
    acc += x[ub + 32 + lane] * x[ib + 32 + lane];
    acc += g_ego1[ub + lane]      * g_ego1[ib + lane];
    acc += g_ego1[ub + 32 + lane] * g_ego1[ib + 32 + lane];
    acc += g_ego2[ub + lane]      * g_ego2[ib + lane];
    acc += g_ego2[ub + 32 + lane] * g_ego2[ib + 32 + lane];
#pragma unroll
    for (int o = 16; o > 0; o >>= 1)
        acc += __shfl_xor_sync(0xffffffffu, acc, o);
    if (lane == 0) out[b] = acc;
}

// ---------------------------------------------------------------------------
extern "C" void kernel_launch(void* const* d_in, const int* in_sizes, int n_in,
                              void* d_out, int out_size) {
    const int*   rows = (const int*)d_in[0];
    const int*   cols = (const int*)d_in[1];
    const float* vals = (const float*)d_in[2];
    const float* x    = (const float*)d_in[3];

    const float *Wg0, *bg0, *Wb0, *bb0, *Wg1, *bg1, *Wb1, *bb1;
    const int *users, *items;
    if (in_sizes[4] == BATCH_C) {
        users = (const int*)d_in[4];
        items = (const int*)d_in[5];
        Wg0 = (const float*)d_in[6];  bg0 = (const float*)d_in[7];
        Wb0 = (const float*)d_in[8];  bb0 = (const float*)d_in[9];
        Wg1 = (const float*)d_in[10]; bg1 = (const float*)d_in[11];
        Wb1 = (const float*)d_in[12]; bb1 = (const float*)d_in[13];
    } else {
        Wg0 = (const float*)d_in[4];  bg0 = (const float*)d_in[5];
        Wb0 = (const float*)d_in[6];  bb0 = (const float*)d_in[7];
        Wg1 = (const float*)d_in[8];  bg1 = (const float*)d_in[9];
        Wb1 = (const float*)d_in[10]; bb1 = (const float*)d_in[11];
        users = (const int*)d_in[12];
        items = (const int*)d_in[13];
    }

    float *side, *ego1, *ego2;
    uint2 *egoh;
    int *cnt, *wpos, *agg, *flag;
    int2 *epack;
    cudaGetSymbolAddress((void**)&side,  g_side);
    cudaGetSymbolAddress((void**)&ego1,  g_ego1);
    cudaGetSymbolAddress((void**)&ego2,  g_ego2);
    cudaGetSymbolAddress((void**)&egoh,  g_egoh);
    cudaGetSymbolAddress((void**)&cnt,   g_cnt);
    cudaGetSymbolAddress((void**)&wpos,  g_wpos);
    cudaGetSymbolAddress((void**)&agg,   g_agg);
    cudaGetSymbolAddress((void**)&flag,  g_flag);
    cudaGetSymbolAddress((void**)&epack, g_epack);

    int smemBytes = (KDIM_C * D_C + TM_C * INS_C + 64) * (int)sizeof(float);
    cudaFuncSetAttribute(dense_kernel, cudaFuncAttributeMaxDynamicSharedMemorySize, smemBytes);

    int numTiles   = (N_NODES_C + TM_C - 1) / TM_C;       // 2344
    int edgeBlocks = (NNZ_C + 255) / 256;                 // 9375
    int z4 = N_NODES_C * 16;
    int zeroBlocks = (z4 + 255) / 256;                    // 9375
    int spmmBlocks = NNZ_C / EPB_C;                       // 9375

    // 0: zero cnt + side + flags     1: fp16 copy of x
    pre_kernel<<<zeroBlocks, 256>>>(cnt, (float4*)side, flag, z4);
    f2h_kernel<<<zeroBlocks, 256>>>((const float4*)x, egoh, z4);
    // 2-4: build row-grouped packed edge list
    hist_kernel<<<edgeBlocks, 256>>>(rows, cnt);
    scan_fused_kernel<<<NBLK_SCAN, SCB>>>(cnt, wpos, agg, flag);
    reorder_kernel<<<edgeBlocks, 256>>>(rows, cols, vals, wpos, epack);
    // 5: layer-1 SpMM (ncu -s 5 lands here)
    seg_spmm_h_kernel<<<spmmBlocks, 256>>>(epack, egoh, (float4*)side);
    // 6: layer-1 dense
    dense_kernel<<<592, 256, smemBytes>>>((const float4*)side, (const float4*)x,
                                          (const float4*)Wg0, bg0,
                                          (const float4*)Wb0, bb0,
                                          (float4*)ego1, numTiles);
    // 7-9: layer 2
    f2h_zero_kernel<<<zeroBlocks, 256>>>((const float4*)ego1, egoh, (float4*)side, z4);
    seg_spmm_h_kernel<<<spmmBlocks, 256>>>(epack, egoh, (float4*)side);
    dense_kernel<<<592, 256, smemBytes>>>((const float4*)side, (const float4*)ego1,
                                          (const float4*)Wg1, bg1,
                                          (const float4*)Wb1, bb1,
                                          (float4*)ego2, numTiles);
    // 10: final BPR scores
    gamma_kernel<<<BATCH_C / 8, 256>>>(x, users, items, (float*)d_out);
}

// round 12
// speedup vs baseline: 1.9178x; 1.6146x over previous
#include <cuda_runtime.h>
#include <cuda_fp16.h>
#include <mma.h>
#include <math.h>
#include <stdint.h>

using namespace nvcuda;

#define N_USERS_C 100000
#define N_ITEMS_C 50000
#define N_NODES_C 150000
#define D_C 64
#define NNZ_C 2400000
#define BATCH_C 2048
#define SCB 256
#define NBLK_SCAN ((N_NODES_C + SCB - 1) / SCB)   // 586

// Scratch buffers (allocation-free rule: device globals)
__device__ float g_side[N_NODES_C * D_C];
__device__ float g_ego1[N_NODES_C * D_C];
__device__ float g_ego2[N_NODES_C * D_C];
__device__ uint2 g_egoh[N_NODES_C * 16];  // fp16 copy of current ego
__device__ int   g_cnt[N_NODES_C];
__device__ int   g_wpos[N_NODES_C];
__device__ int   g_agg[1024];
__device__ int   g_flag[1024];
__device__ int2  g_epack[NNZ_C];          // packed (row18,col18,val16) by row

// ---------------------------------------------------------------------------
// pre: zero cnt + side accumulator + scan flags (one streaming kernel)
// ---------------------------------------------------------------------------
__global__ void pre_kernel(int* __restrict__ cnt, float4* __restrict__ side,
                           int* __restrict__ flag, int n4) {
    int i = blockIdx.x * blockDim.x + threadIdx.x;
    if (i < n4) side[i] = make_float4(0.f, 0.f, 0.f, 0.f);
    if (i < N_NODES_C) cnt[i] = 0;
    if (i < 1024) flag[i] = 0;
}

// ---------------------------------------------------------------------------
// fp32 -> fp16 conversion (streaming); optional side zeroing fused
// ---------------------------------------------------------------------------
__global__ void f2h_kernel(const float4* __restrict__ in, uint2* __restrict__ out, int n4) {
    int i = blockIdx.x * blockDim.x + threadIdx.x;
    if (i >= n4) return;
    float4 v = in[i];
    __half2 a = __floats2half2_rn(v.x, v.y);
    __half2 b = __floats2half2_rn(v.z, v.w);
    uint2 o;
    o.x = *reinterpret_cast<unsigned*>(&a);
    o.y = *reinterpret_cast<unsigned*>(&b);
    out[i] = o;
}

__global__ void f2h_zero_kernel(const float4* __restrict__ in, uint2* __restrict__ out,
                                float4* __restrict__ side, int n4) {
    int i = blockIdx.x * blockDim.x + threadIdx.x;
    if (i >= n4) return;
    float4 v = in[i];
    __half2 a = __floats2half2_rn(v.x, v.y);
    __half2 b = __floats2half2_rn(v.z, v.w);
    uint2 o;
    o.x = *reinterpret_cast<unsigned*>(&a);
    o.y = *reinterpret_cast<unsigned*>(&b);
    out[i] = o;
    side[i] = make_float4(0.f, 0.f, 0.f, 0.f);
}

// ---------------------------------------------------------------------------
// Histogram of row degrees
// ---------------------------------------------------------------------------
__global__ void hist_kernel(const int* __restrict__ rows, int* __restrict__ cnt) {
    int e = blockIdx.x * blockDim.x + threadIdx.x;
    if (e < NNZ_C) atomicAdd(&cnt[rows[e]], 1);
}

// ---------------------------------------------------------------------------
// Single-pass scan with decoupled aggregates
// ---------------------------------------------------------------------------
__global__ __launch_bounds__(SCB)
void scan_fused_kernel(const int* __restrict__ cnt, int* __restrict__ wpos,
                       int* __restrict__ agg, int* __restrict__ flag) {
    __shared__ int s[SCB];
    __shared__ int prefixSh;
    int b = blockIdx.x;
    int tid = threadIdx.x;
    int i = b * SCB + tid;
    int v = (i < N_NODES_C) ? cnt[i] : 0;
    s[tid] = v;
    __syncthreads();
    for (int o = 1; o < SCB; o <<= 1) {
        int a = (tid >= o) ? s[tid - o] : 0;
        __syncthreads();
        s[tid] += a;
        __syncthreads();
    }
    int incl = s[tid];
    if (tid == SCB - 1) {
        agg[b] = incl;
        __threadfence();
        flag[b] = 1;
    }
    if (tid < 32) {
        int sum = 0;
        for (int j = tid; j < b; j += 32) {
            while (((volatile int*)flag)[j] == 0) {}
            sum += ((volatile int*)agg)[j];
        }
#pragma unroll
        for (int o = 16; o > 0; o >>= 1)
            sum += __shfl_xor_sync(0xffffffffu, sum, o);
        if (tid == 0) prefixSh = sum;
    }
    __syncthreads();
    if (i < N_NODES_C) wpos[i] = prefixSh + incl - v;
}

// ---------------------------------------------------------------------------
// Reorder into row-grouped packed int2
// ---------------------------------------------------------------------------
__global__ void reorder_kernel(const int* __restrict__ rows,
                               const int* __restrict__ cols,
                               const float* __restrict__ vals,
                               int* __restrict__ wpos,
                               int2* __restrict__ epack) {
    int e = blockIdx.x * blockDim.x + threadIdx.x;
    if (e >= NNZ_C) return;
    int r = rows[e];
    int p = atomicAdd(&wpos[r], 1);
    unsigned short hv = __half_as_ushort(__float2half_rn(vals[e]));
    int w0 = cols[e] | ((r & 0x3FFF) << 18);
    int w1 = (r >> 14) | ((int)hv << 16);
    epack[p] = make_int2(w0, w1);
}

// ---------------------------------------------------------------------------
// Segmented SpMM over row-sorted packed edges, fp16 gather (best config)
// ---------------------------------------------------------------------------
#define EPS_C 16
#define EPB_C 256

__device__ __forceinline__ void red_v4(float4* dst, float4 a) {
    asm volatile("red.global.add.v4.f32 [%0], {%1, %2, %3, %4};"
                 :: "l"(dst), "f"(a.x), "f"(a.y), "f"(a.z), "f"(a.w)
                 : "memory");
}

__global__ __launch_bounds__(256)
void seg_spmm_h_kernel(const int2* __restrict__ epack,
                       const uint2* __restrict__ egoh,
                       float4* __restrict__ side) {
    int tid  = threadIdx.x;
    int slot = tid >> 4;
    int lane = tid & 15;
    int half = (tid & 31) >= 16 ? 16 : 0;
    int e0 = blockIdx.x * EPB_C + slot * EPS_C;

    int2 ep = epack[e0 + lane];

    float4 acc = make_float4(0.f, 0.f, 0.f, 0.f);
    int cur = -1;

#pragma unroll
    for (int b = 0; b < 4; b++) {
        int rr[4]; float vv[4]; uint2 gh[4];
#pragma unroll
        for (int u = 0; u < 4; u++) {
            int src = half + b * 4 + u;
            int w0 = __shfl_sync(0xffffffffu, ep.x, src);
            int w1 = __shfl_sync(0xffffffffu, ep.y, src);
            int c  = w0 & 0x3FFFF;
            rr[u]  = ((w0 >> 18) & 0x3FFF) | ((w1 & 0xF) << 14);
            vv[u]  = __half2float(__ushort_as_half((unsigned short)((unsigned)w1 >> 16)));
            gh[u]  = egoh[c * 16 + lane];
        }
#pragma unroll
        for (int u = 0; u < 4; u++) {
            if (rr[u] != cur) {
                if (cur >= 0) red_v4(&side[cur * 16 + lane], acc);
                acc = make_float4(0.f, 0.f, 0.f, 0.f);
                cur = rr[u];
            }
            __half2 h01 = *reinterpret_cast<__half2*>(&gh[u].x);
            __half2 h23 = *reinterpret_cast<__half2*>(&gh[u].y);
            float2 f01 = __half22float2(h01);
            float2 f23 = __half22float2(h23);
            acc.x = fmaf(vv[u], f01.x, acc.x);
            acc.y = fmaf(vv[u], f01.y, acc.y);
            acc.z = fmaf(vv[u], f23.x, acc.z);
            acc.w = fmaf(vv[u], f23.y, acc.w);
        }
    }
    if (cur >= 0)
        red_v4(&side[cur * 16 + lane], acc);
}

// ---------------------------------------------------------------------------
// Dense layer via tensor cores (HMMA fp16 in / fp32 accumulate):
// out = l2norm(leaky_relu(side@Wg + (ego*side)@Wb + bg + bb))
// Tile: 64 rows x 64 cols, K = 128 ([side | ego*side] in fp16 smem).
// 128 threads = 4 warps; warp w computes rows 16w..16w+15 via m16n16k16.
// ---------------------------------------------------------------------------
#define TM_C 64
#define KDIM_C 128
#define LDA_C 136   // half stride for A tile (mult of 8)
#define LDB_C 72    // half stride for B tile (mult of 8)

__global__ __launch_bounds__(128)
void dense_kernel(const float4* __restrict__ side,
                  const float4* __restrict__ ego,
                  const float4* __restrict__ Wg, const float* __restrict__ bg,
                  const float4* __restrict__ Wb, const float* __restrict__ bb,
                  float4* __restrict__ out, int numTiles) {
    extern __shared__ char smem[];
    __half* A   = (__half*)smem;                               // [64][136] halves
    __half* B   = (__half*)(smem + TM_C * LDA_C * 2);          // [128][72] halves
    float*  C   = (float*)(smem + TM_C * LDA_C * 2 + KDIM_C * LDB_C * 2);  // [64][64]
    float*  bsum = C + TM_C * D_C;                             // [64]

    int tid = threadIdx.x;
    int wid = tid >> 5;

    // Stage combined weights [Wg ; Wb] -> fp16 B tile (once per block)
#pragma unroll
    for (int i = 0; i < 16; i++) {
        int f = tid + i * 128;               // float4 index 0..2047
        int k = f >> 4, c4 = f & 15;
        float4 w = (k < 64) ? Wg[k * 16 + c4] : Wb[(k - 64) * 16 + c4];
        __half2* dst = (__half2*)&B[k * LDB_C + c4 * 4];
        dst[0] = __floats2half2_rn(w.x, w.y);
        dst[1] = __floats2half2_rn(w.z, w.w);
    }
    if (tid < 64) bsum[tid] = bg[tid] + bb[tid];
    __syncthreads();

    for (int tile = blockIdx.x; tile < numTiles; tile += gridDim.x) {
        int row0 = tile * TM_C;

        // Stage A tile: [r][0:64]=side (fp16), [r][64:128]=ego*side (fp16)
#pragma unroll
        for (int i = 0; i < 8; i++) {
            int f = tid + i * 128;           // 0..1023 over 64 rows x 16 f4
            int r = f >> 4, k4 = f & 15;
            float4 s  = make_float4(0.f, 0.f, 0.f, 0.f);
            float4 pr = make_float4(0.f, 0.f, 0.f, 0.f);
            int grow = row0 + r;
            if (grow < N_NODES_C) {
                s = side[grow * 16 + k4];
                float4 e = ego[grow * 16 + k4];
                pr = make_float4(s.x * e.x, s.y * e.y, s.z * e.z, s.w * e.w);
            }
            __half2* dS = (__half2*)&A[r * LDA_C + k4 * 4];
            dS[0] = __floats2half2_rn(s.x, s.y);
            dS[1] = __floats2half2_rn(s.z, s.w);
            __half2* dP = (__half2*)&A[r * LDA_C + 64 + k4 * 4];
            dP[0] = __floats2half2_rn(pr.x, pr.y);
            dP[1] = __floats2half2_rn(pr.z, pr.w);
        }
        __syncthreads();

        // MMA: warp wid computes rows 16*wid..+15, all 64 cols
        {
            wmma::fragment<wmma::accumulator, 16, 16, 16, float> c_frag[4];
#pragma unroll
            for (int n = 0; n < 4; n++) wmma::fill_fragment(c_frag[n], 0.f);
#pragma unroll
            for (int k = 0; k < KDIM_C / 16; k++) {
                wmma::fragment<wmma::matrix_a, 16, 16, 16, __half, wmma::row_major> a_frag;
                wmma::load_matrix_sync(a_frag, &A[(16 * wid) * LDA_C + k * 16], LDA_C);
#pragma unroll
                for (int n = 0; n < 4; n++) {
                    wmma::fragment<wmma::matrix_b, 16, 16, 16, __half, wmma::row_major> b_frag;
                    wmma::load_matrix_sync(b_frag, &B[(k * 16) * LDB_C + n * 16], LDB_C);
                    wmma::mma_sync(c_frag[n], a_frag, b_frag, c_frag[n]);
                }
            }
#pragma unroll
            for (int n = 0; n < 4; n++)
                wmma::store_matrix_sync(&C[(16 * wid) * D_C + n * 16], c_frag[n],
                                        D_C, wmma::mem_row_major);
        }
        __syncthreads();

        // Epilogue: 2 threads per row (32 cols each): bias, leaky, L2-norm
        {
            int row = tid >> 1;
            int hs  = tid & 1;
            const float* Crow = C + row * D_C + hs * 32;
            const float* brow = bsum + hs * 32;
            float vbuf[32];
            float ss = 0.f;
#pragma unroll
            for (int j = 0; j < 32; j++) {
                float v = Crow[j] + brow[j];
                v = (v > 0.f) ? v : 0.2f * v;
                vbuf[j] = v;
                ss += v * v;
            }
            ss += __shfl_xor_sync(0xffffffffu, ss, 1);
            float scl = 1.0f / fmaxf(sqrtf(ss), 1e-12f);
            int grow = row0 + row;
            if (grow < N_NODES_C) {
#pragma unroll
                for (int j = 0; j < 8; j++)
                    out[grow * 16 + hs * 8 + j] =
                        make_float4(vbuf[4 * j] * scl, vbuf[4 * j + 1] * scl,
                                    vbuf[4 * j + 2] * scl, vbuf[4 * j + 3] * scl);
            }
        }
        __syncthreads();   // C/A reused next tile
    }
}

// ---------------------------------------------------------------------------
// gamma[b] = sum over 3 embeddings of dot(emb[u], emb[N_USERS+item])
// ---------------------------------------------------------------------------
__global__ void gamma_kernel(const float* __restrict__ x,
                             const int* __restrict__ users,
                             const int* __restrict__ items,
                             float* __restrict__ out) {
    int b = blockIdx.x * 8 + (threadIdx.x >> 5);
    if (b >= BATCH_C) return;
    int lane = threadIdx.x & 31;
    int u  = users[b];
    int it = N_USERS_C + items[b];
    long long ub = (long long)u * D_C, ib = (long long)it * D_C;
    float acc = 0.f;
    acc += x[ub + lane]      * x[ib + lane];
    acc += x[ub + 32 + lane] * x[ib + 32 + lane];
    acc += g_ego1[ub + lane]      * g_ego1[ib + lane];
    acc += g_ego1[ub + 32 + lane] * g_ego1[ib + 32 + lane];
    acc += g_ego2[ub + lane]      * g_ego2[ib + lane];
    acc += g_ego2[ub + 32 + lane] * g_ego2[ib + 32 + lane];
#pragma unroll
    for (int o = 16; o > 0; o >>= 1)
        acc += __shfl_xor_sync(0xffffffffu, acc, o);
    if (lane == 0) out[b] = acc;
}

// ---------------------------------------------------------------------------
extern "C" void kernel_launch(void* const* d_in, const int* in_sizes, int n_in,
                              void* d_out, int out_size) {
    const int*   rows = (const int*)d_in[0];
    const int*   cols = (const int*)d_in[1];
    const float* vals = (const float*)d_in[2];
    const float* x    = (const float*)d_in[3];

    const float *Wg0, *bg0, *Wb0, *bb0, *Wg1, *bg1, *Wb1, *bb1;
    const int *users, *items;
    if (in_sizes[4] == BATCH_C) {
        users = (const int*)d_in[4];
        items = (const int*)d_in[5];
        Wg0 = (const float*)d_in[6];  bg0 = (const float*)d_in[7];
        Wb0 = (const float*)d_in[8];  bb0 = (const float*)d_in[9];
        Wg1 = (const float*)d_in[10]; bg1 = (const float*)d_in[11];
        Wb1 = (const float*)d_in[12]; bb1 = (const float*)d_in[13];
    } else {
        Wg0 = (const float*)d_in[4];  bg0 = (const float*)d_in[5];
        Wb0 = (const float*)d_in[6];  bb0 = (const float*)d_in[7];
        Wg1 = (const float*)d_in[8];  bg1 = (const float*)d_in[9];
        Wb1 = (const float*)d_in[10]; bb1 = (const float*)d_in[11];
        users = (const int*)d_in[12];
        items = (const int*)d_in[13];
    }

    float *side, *ego1, *ego2;
    uint2 *egoh;
    int *cnt, *wpos, *agg, *flag;
    int2 *epack;
    cudaGetSymbolAddress((void**)&side,  g_side);
    cudaGetSymbolAddress((void**)&ego1,  g_ego1);
    cudaGetSymbolAddress((void**)&ego2,  g_ego2);
    cudaGetSymbolAddress((void**)&egoh,  g_egoh);
    cudaGetSymbolAddress((void**)&cnt,   g_cnt);
    cudaGetSymbolAddress((void**)&wpos,  g_wpos);
    cudaGetSymbolAddress((void**)&agg,   g_agg);
    cudaGetSymbolAddress((void**)&flag,  g_flag);
    cudaGetSymbolAddress((void**)&epack, g_epack);

    // dense smem: A (64*136*2) + B (128*72*2) + C (64*64*4) + bias (64*4)
    int denseSmem = TM_C * LDA_C * 2 + KDIM_C * LDB_C * 2 + TM_C * D_C * 4 + 64 * 4;
    cudaFuncSetAttribute(dense_kernel, cudaFuncAttributeMaxDynamicSharedMemorySize, denseSmem);

    int numTiles   = (N_NODES_C + TM_C - 1) / TM_C;       // 2344
    int edgeBlocks = (NNZ_C + 255) / 256;                 // 9375
    int z4 = N_NODES_C * 16;
    int zeroBlocks = (z4 + 255) / 256;                    // 9375
    int spmmBlocks = NNZ_C / EPB_C;                       // 9375

    pre_kernel<<<zeroBlocks, 256>>>(cnt, (float4*)side, flag, z4);
    f2h_kernel<<<zeroBlocks, 256>>>((const float4*)x, egoh, z4);
    hist_kernel<<<edgeBlocks, 256>>>(rows, cnt);
    scan_fused_kernel<<<NBLK_SCAN, SCB>>>(cnt, wpos, agg, flag);
    reorder_kernel<<<edgeBlocks, 256>>>(rows, cols, vals, wpos, epack);
    // Layer 1
    seg_spmm_h_kernel<<<spmmBlocks, 256>>>(epack, egoh, (float4*)side);
    dense_kernel<<<592, 128, denseSmem>>>((const float4*)side, (const float4*)x,
                                          (const float4*)Wg0, bg0,
                                          (const float4*)Wb0, bb0,
                                          (float4*)ego1, numTiles);
    // Layer 2
    f2h_zero_kernel<<<zeroBlocks, 256>>>((const float4*)ego1, egoh, (float4*)side, z4);
    seg_spmm_h_kernel<<<spmmBlocks, 256>>>(epack, egoh, (float4*)side);
    dense_kernel<<<592, 128, denseSmem>>>((const float4*)side, (const float4*)ego1,
                                          (const float4*)Wg1, bg1,
                                          (const float4*)Wb1, bb1,
                                          (float4*)ego2, numTiles);
    // Final BPR scores
    gamma_kernel<<<BATCH_C / 8, 256>>>(x, users, items, (float*)d_out);
}